// round 6
// baseline (speedup 1.0000x reference)
#include <cuda_runtime.h>
#include <cuda_bf16.h>
#include <cstdint>
#include <math.h>

#define NROWS 8192
#define D     512
#define CB    4096
#define FB    8192
#define BM    128
#define BN    128
#define KC    64
#define NCH   (D / KC)
#define THRESH 3e-4f
#define SMEM_DYN 65536

typedef unsigned long long ull;

__device__ float g_nsq_c[CB];
__device__ float g_nsq_f[FB];
__device__ float g_xnsq_c[NROWS];
__device__ float g_xnsq_f[NROWS];
__device__ ull   g_b1c[NROWS], g_b2c[NROWS];
__device__ ull   g_b1f[NROWS], g_b2f[NROWS];
__device__ int   g_idx_c[NROWS], g_idx_f[NROWS];
__device__ float g_qc[NROWS * D];
__device__ float g_qf[NROWS * D];
__device__ float g_ci[NROWS * D];
__device__ float g_res[NROWS * D];
__device__ float g_h[NROWS * D];
__device__ float g_loss;

// ---------------- helpers ----------------
__device__ __forceinline__ uint32_t smem_u32(const void* p) {
    uint32_t a;
    asm("{ .reg .u64 t; cvta.to.shared.u64 t, %1; cvt.u32.u64 %0, t; }" : "=r"(a) : "l"(p));
    return a;
}
#define SWZ(o) ((o) ^ (((o) >> 3) & 0x70))
#define LDM4(r0, r1, r2, r3, a) \
    asm volatile("ldmatrix.sync.aligned.m8n8.x4.shared.b16 {%0,%1,%2,%3}, [%4];" \
        : "=r"(r0), "=r"(r1), "=r"(r2), "=r"(r3) : "r"(a))
#define MMA_BF16(c, a, b) \
    asm volatile("mma.sync.aligned.m16n8k16.row.col.f32.bf16.bf16.f32 " \
        "{%0,%1,%2,%3}, {%4,%5,%6,%7}, {%8,%9}, {%0,%1,%2,%3};" \
        : "+f"((c)[0]), "+f"((c)[1]), "+f"((c)[2]), "+f"((c)[3]) \
        : "r"((a)[0]), "r"((a)[1]), "r"((a)[2]), "r"((a)[3]), "r"((b)[0]), "r"((b)[1]))

__device__ __forceinline__ uint32_t bf2(float lo, float hi) { // mem order: lo in low half
    uint32_t r;
    asm("cvt.rn.bf16x2.f32 %0, %1, %2;" : "=r"(r) : "f"(hi), "f"(lo));
    return r;
}
__device__ __forceinline__ float bhi(float x) {
    return __bfloat162float(__float2bfloat16(x));
}
__device__ __forceinline__ ull packdi(float d, unsigned j) {
    unsigned u = __float_as_uint(d);
    u = (u & 0x80000000u) ? ~u : (u | 0x80000000u);
    return ((ull)u << 32) | (ull)j;
}
__device__ __forceinline__ float unpackd(ull p) {
    unsigned u = (unsigned)(p >> 32);
    u = (u & 0x80000000u) ? (u & 0x7fffffffu) : ~u;
    return __uint_as_float(u);
}
__device__ __forceinline__ void top2ins(ull& m1, ull& m2, ull p) {
    if (p < m1) { m2 = m1; m1 = p; }
    else if (p < m2) m2 = p;
}

// ---------------- prep ----------------
__global__ void prep_kernel(const float* __restrict__ z,
                            const float* __restrict__ ce, const float* __restrict__ fe) {
    int tid = blockIdx.x * blockDim.x + threadIdx.x;
    int w = tid >> 5, lane = tid & 31;
    if (w < CB + FB + NROWS) {
        const float* src;
        if (w < CB)           src = ce + (size_t)w * D;
        else if (w < CB + FB) src = fe + (size_t)(w - CB) * D;
        else                  src = z + (size_t)(w - CB - FB) * 1024;
        float s = 0.f;
        #pragma unroll
        for (int it = 0; it < 4; it++) {
            float4 v = *(const float4*)(src + lane * 4 + it * 128);
            s += v.x * v.x + v.y * v.y + v.z * v.z + v.w * v.w;
        }
        #pragma unroll
        for (int o = 16; o; o >>= 1) s += __shfl_xor_sync(0xffffffffu, s, o);
        if (lane == 0) {
            if (w < CB)           g_nsq_c[w] = s;
            else if (w < CB + FB) g_nsq_f[w - CB] = s;
            else                  g_xnsq_c[w - CB - FB] = s;
        }
    }
    if (tid < NROWS) {
        g_b1c[tid] = ~0ull; g_b2c[tid] = ~0ull;
        g_b1f[tid] = ~0ull; g_b2f[tid] = ~0ull;
    }
    if (tid == 0) g_loss = 0.f;
}

// ---------------- HMMA bf16 3-pass GEMM ----------------
// MODE 0: VQ (global top-2 of d = fl(fl(xx+ee) - 2*dot)) ; MODE 1: out = dot + bias
// A: [M][K] stride lda ; B: [NB][512] row-major
template <int MODE>
__global__ __launch_bounds__(256, 2) void mma_gemm(
    const float* __restrict__ A, int lda,
    const float* __restrict__ B,
    const float* __restrict__ aux, const float* __restrict__ xnsq,
    ull* __restrict__ best1, ull* __restrict__ best2,
    float* __restrict__ out)
{
    extern __shared__ char sm[];
    __shared__ ull sb1[BM], sb2[BM];
    const int t = threadIdx.x;
    const int lane = t & 31, wid = t >> 5;
    const int warp_m = wid & 1, warp_n = wid >> 1;
    const int row0 = blockIdx.x * BM, col0 = blockIdx.y * BN;
    const uint32_t smb = smem_u32(sm);
    const uint32_t AH = smb, AL = smb + 16384u, BH = smb + 32768u, BL = smb + 49152u;

    if (MODE == 0 && t < BM) { sb1[t] = ~0ull; sb2[t] = ~0ull; }

    float acc[4][4][4];
    #pragma unroll
    for (int i = 0; i < 4; i++)
        #pragma unroll
        for (int j = 0; j < 4; j++)
            #pragma unroll
            for (int k = 0; k < 4; k++) acc[i][j][k] = 0.f;

    const int lrow = t >> 1, lhalf = t & 1;
    const float* apr = A + (size_t)(row0 + lrow) * lda + lhalf * 32;
    const float* bpr = B + (size_t)(col0 + lrow) * D + lhalf * 32;
    const uint32_t stbase = (uint32_t)(lrow * 128 + lhalf * 64);

    #pragma unroll 1
    for (int c = 0; c < NCH; c++) {
        const int kb = c * KC;
        // ---- load + split fp32 -> bf16 hi/lo into SW128 smem ----
        #pragma unroll
        for (int it = 0; it < 4; it++) {
            const int kl = it * 8;
            const uint32_t off = SWZ(stbase + kl * 2);
            float4 v0 = *(const float4*)(apr + kb + kl);
            float4 v1 = *(const float4*)(apr + kb + kl + 4);
            float h0 = bhi(v0.x), h1 = bhi(v0.y), h2 = bhi(v0.z), h3 = bhi(v0.w);
            float h4 = bhi(v1.x), h5 = bhi(v1.y), h6 = bhi(v1.z), h7 = bhi(v1.w);
            uint4 H = { bf2(h0, h1), bf2(h2, h3), bf2(h4, h5), bf2(h6, h7) };
            uint4 L = { bf2(v0.x - h0, v0.y - h1), bf2(v0.z - h2, v0.w - h3),
                        bf2(v1.x - h4, v1.y - h5), bf2(v1.z - h6, v1.w - h7) };
            *(uint4*)(sm + (AH - smb) + off) = H;
            *(uint4*)(sm + (AL - smb) + off) = L;
            float4 w0 = *(const float4*)(bpr + kb + kl);
            float4 w1 = *(const float4*)(bpr + kb + kl + 4);
            float j0 = bhi(w0.x), j1 = bhi(w0.y), j2 = bhi(w0.z), j3 = bhi(w0.w);
            float j4 = bhi(w1.x), j5 = bhi(w1.y), j6 = bhi(w1.z), j7 = bhi(w1.w);
            uint4 BHv = { bf2(j0, j1), bf2(j2, j3), bf2(j4, j5), bf2(j6, j7) };
            uint4 BLv = { bf2(w0.x - j0, w0.y - j1), bf2(w0.z - j2, w0.w - j3),
                          bf2(w1.x - j4, w1.y - j5), bf2(w1.z - j6, w1.w - j7) };
            *(uint4*)(sm + (BH - smb) + off) = BHv;
            *(uint4*)(sm + (BL - smb) + off) = BLv;
        }
        __syncthreads();
        // ---- compute: 3 passes (hh, hl, lh) ----
        #pragma unroll
        for (int k16 = 0; k16 < 4; k16++) {
            uint32_t bhf[4][2], blf[4][2];
            #pragma unroll
            for (int nt2 = 0; nt2 < 2; nt2++) {
                int nrow = warp_n * 32 + nt2 * 16 + (lane & 7) + ((lane & 16) ? 8 : 0);
                int kbyte = k16 * 32 + ((lane >> 3) & 1) * 16;
                uint32_t off = SWZ((uint32_t)(nrow * 128 + kbyte));
                LDM4(bhf[nt2 * 2][0], bhf[nt2 * 2][1], bhf[nt2 * 2 + 1][0], bhf[nt2 * 2 + 1][1], BH + off);
                LDM4(blf[nt2 * 2][0], blf[nt2 * 2][1], blf[nt2 * 2 + 1][0], blf[nt2 * 2 + 1][1], BL + off);
            }
            #pragma unroll
            for (int mt = 0; mt < 4; mt++) {
                int mrow = warp_m * 64 + mt * 16 + (lane & 15);
                int kbyte = k16 * 32 + (lane >> 4) * 16;
                uint32_t off = SWZ((uint32_t)(mrow * 128 + kbyte));
                uint32_t ah[4], al[4];
                LDM4(ah[0], ah[1], ah[2], ah[3], AH + off);
                #pragma unroll
                for (int nt = 0; nt < 4; nt++) MMA_BF16(acc[mt][nt], ah, bhf[nt]);
                #pragma unroll
                for (int nt = 0; nt < 4; nt++) MMA_BF16(acc[mt][nt], ah, blf[nt]);
                LDM4(al[0], al[1], al[2], al[3], AL + off);
                #pragma unroll
                for (int nt = 0; nt < 4; nt++) MMA_BF16(acc[mt][nt], al, bhf[nt]);
            }
        }
        __syncthreads();
    }

    // ---- epilogue ----
    const int g = lane >> 2, tg = lane & 3;
    if (MODE == 0) {
        #pragma unroll
        for (int mt = 0; mt < 4; mt++) {
            #pragma unroll
            for (int h8 = 0; h8 < 2; h8++) {
                int lrow2 = warp_m * 64 + mt * 16 + g + h8 * 8;
                float xx = xnsq[row0 + lrow2];
                ull m1 = ~0ull, m2 = ~0ull;
                #pragma unroll
                for (int nt = 0; nt < 4; nt++) {
                    int colg = col0 + warp_n * 32 + nt * 8 + tg * 2;
                    float d0 = __fadd_rn(__fadd_rn(xx, aux[colg]), -2.f * acc[mt][nt][h8 * 2 + 0]);
                    float d1 = __fadd_rn(__fadd_rn(xx, aux[colg + 1]), -2.f * acc[mt][nt][h8 * 2 + 1]);
                    top2ins(m1, m2, packdi(d0, (unsigned)colg));
                    top2ins(m1, m2, packdi(d1, (unsigned)(colg + 1)));
                }
                #pragma unroll
                for (int o = 1; o <= 2; o <<= 1) {
                    ull o1 = __shfl_xor_sync(0xffffffffu, m1, o);
                    ull o2 = __shfl_xor_sync(0xffffffffu, m2, o);
                    ull n1 = o1 < m1 ? o1 : m1;
                    ull hi = o1 > m1 ? o1 : m1;
                    ull lo2 = o2 < m2 ? o2 : m2;
                    m2 = hi < lo2 ? hi : lo2;
                    m1 = n1;
                }
                if (tg == 0) {
                    ull old = atomicMin(&sb1[lrow2], m1);
                    atomicMin(&sb2[lrow2], old > m1 ? old : m1);
                    atomicMin(&sb2[lrow2], m2);
                }
            }
        }
        __syncthreads();
        if (t < BM) {
            ull s1 = sb1[t], s2 = sb2[t];
            ull old = atomicMin(&best1[row0 + t], s1);
            atomicMin(&best2[row0 + t], old > s1 ? old : s1);
            atomicMin(&best2[row0 + t], s2);
        }
    } else {
        #pragma unroll
        for (int mt = 0; mt < 4; mt++) {
            #pragma unroll
            for (int h8 = 0; h8 < 2; h8++) {
                int row = row0 + warp_m * 64 + mt * 16 + g + h8 * 8;
                #pragma unroll
                for (int nt = 0; nt < 4; nt++) {
                    int colg = col0 + warp_n * 32 + nt * 8 + tg * 2;
                    float2 o2 = make_float2(acc[mt][nt][h8 * 2 + 0] + aux[colg],
                                            acc[mt][nt][h8 * 2 + 1] + aux[colg + 1]);
                    *(float2*)&out[(size_t)row * D + colg] = o2;
                }
            }
        }
    }
}

// ---------------- fixup: exact fp32 re-decide for near-tie rows ----------------
__global__ void fixup_kernel(const float* __restrict__ A, int lda,
                             const float* __restrict__ B, int NB,
                             const float* __restrict__ nsq, const float* __restrict__ xnsq,
                             const ull* __restrict__ b1, const ull* __restrict__ b2,
                             int* __restrict__ idxout)
{
    int r = blockIdx.x;
    ull p1 = b1[r], p2 = b2[r];
    if (unpackd(p2) - unpackd(p1) > THRESH) {
        if (threadIdx.x == 0) idxout[r] = (int)(p1 & 0xffffffffu);
        return;
    }
    __shared__ float xs[D];
    __shared__ ull wmin[8];
    for (int k = threadIdx.x; k < D; k += 256) xs[k] = A[(size_t)r * lda + k];
    __syncthreads();
    float xx = xnsq[r];
    int lane = threadIdx.x & 31, w = threadIdx.x >> 5;
    ull m = ~0ull;
    for (int j = w; j < NB; j += 8) {
        const float* e = B + (size_t)j * D;
        float s = 0.f;
        for (int k = lane; k < D; k += 32) s = fmaf(e[k], xs[k], s);
        #pragma unroll
        for (int o = 16; o; o >>= 1) s += __shfl_xor_sync(0xffffffffu, s, o);
        float d = __fadd_rn(__fadd_rn(xx, nsq[j]), -2.f * s);
        ull p = packdi(d, (unsigned)j);
        if (p < m) m = p;
    }
    if (lane == 0) wmin[w] = m;
    __syncthreads();
    if (threadIdx.x == 0) {
        ull mm = wmin[0];
        #pragma unroll
        for (int i = 1; i < 8; i++) if (wmin[i] < mm) mm = wmin[i];
        idxout[r] = (int)(mm & 0xffffffffu);
    }
}

// ---------------- gather q = emb[idx], loss ----------------
__global__ void gather_loss(const float* __restrict__ emb, const int* __restrict__ idx,
                            const float* __restrict__ x, int ldx, float* __restrict__ q)
{
    int r = blockIdx.x;
    int j = idx[r];
    const float* e = emb + (size_t)j * D;
    const float* xr = x + (size_t)r * ldx;
    float* qr = q + (size_t)r * D;
    float ls = 0.f;
    for (int k = threadIdx.x; k < D; k += blockDim.x) {
        float ev = e[k];
        qr[k] = ev;
        float dd = ev - xr[k];
        ls += dd * dd;
    }
    #pragma unroll
    for (int o = 16; o; o >>= 1) ls += __shfl_xor_sync(0xffffffffu, ls, o);
    __shared__ float ws[8];
    int w = threadIdx.x >> 5;
    if ((threadIdx.x & 31) == 0) ws[w] = ls;
    __syncthreads();
    if (threadIdx.x == 0) {
        float s = 0.f;
        for (int i = 0; i < 8; i++) s += ws[i];
        atomicAdd(&g_loss, s);
    }
}

// ---------------- LayerNorm + leakyReLU + fused follow-up ----------------
template <int MODE>
__global__ void ln_kernel(const float* __restrict__ h,
                          const float* __restrict__ g, const float* __restrict__ be,
                          const float* __restrict__ z,
                          const float* __restrict__ gc_raw, const float* __restrict__ gf_raw,
                          float* __restrict__ out)
{
    int r = blockIdx.x;
    int j = threadIdx.x;
    float hv = h[(size_t)r * D + j];
    float s = hv, sq = hv * hv;
    #pragma unroll
    for (int o = 16; o; o >>= 1) {
        s += __shfl_xor_sync(0xffffffffu, s, o);
        sq += __shfl_xor_sync(0xffffffffu, sq, o);
    }
    __shared__ float s1[16], s2[16];
    int w = j >> 5, lane = j & 31;
    if (lane == 0) { s1[w] = s; s2[w] = sq; }
    __syncthreads();
    if (w == 0) {
        s = (lane < 16) ? s1[lane] : 0.f;
        sq = (lane < 16) ? s2[lane] : 0.f;
        #pragma unroll
        for (int o = 8; o; o >>= 1) {
            s += __shfl_xor_sync(0xffffffffu, s, o);
            sq += __shfl_xor_sync(0xffffffffu, sq, o);
        }
        if (lane == 0) { s1[0] = s; s2[0] = sq; }
    }
    __syncthreads();
    float mean = s1[0] * (1.f / D);
    float var = s2[0] * (1.f / D) - mean * mean;
    float y = (hv - mean) * rsqrtf(var + 1e-5f) * g[j] + be[j];
    float act = y > 0.f ? y : 0.1f * y;
    float gcv = 1.f / (1.f + expf(-gc_raw[0]));

    if (MODE == 0) {
        float rv = z[(size_t)r * 1024 + D + j] - gcv * act;
        g_ci[(size_t)r * D + j] = act;
        g_res[(size_t)r * D + j] = rv;
        float rq = rv * rv;
        #pragma unroll
        for (int o = 16; o; o >>= 1) rq += __shfl_xor_sync(0xffffffffu, rq, o);
        __syncthreads();
        if (lane == 0) s1[w] = rq;
        __syncthreads();
        if (j == 0) {
            float tt = 0.f;
            #pragma unroll
            for (int i = 0; i < 16; i++) tt += s1[i];
            g_xnsq_f[r] = tt;
        }
    } else {
        float gfv = 1.f / (1.f + expf(-gf_raw[0]));
        out[(size_t)r * 1024 + j] = g_qc[(size_t)r * D + j] + 0.1f * gfv * act;
        out[(size_t)r * 1024 + D + j] = g_qf[(size_t)r * D + j] + gcv * g_ci[(size_t)r * D + j];
        if (r == 0 && j == 0)
            out[(size_t)NROWS * 1024] = 1.25f * g_loss / (float)((size_t)NROWS * D);
    }
}

// ---------------- launch ----------------
extern "C" void kernel_launch(void* const* d_in, const int* in_sizes, int n_in,
                              void* d_out, int out_size) {
    const float* z      = (const float*)d_in[0];
    const float* ce     = (const float*)d_in[1];
    const float* fe     = (const float*)d_in[2];
    const float* w_c2f  = (const float*)d_in[3];
    const float* b_c2f  = (const float*)d_in[4];
    const float* g_c2f  = (const float*)d_in[5];
    const float* be_c2f = (const float*)d_in[6];
    const float* w_f2c  = (const float*)d_in[7];
    const float* b_f2c  = (const float*)d_in[8];
    const float* g_f2c  = (const float*)d_in[9];
    const float* be_f2c = (const float*)d_in[10];
    const float* gc_raw = (const float*)d_in[11];
    const float* gf_raw = (const float*)d_in[12];
    float* out = (float*)d_out;

    float *nsq_c, *nsq_f, *xnsq_c, *xnsq_f, *qc, *qf, *res, *h;
    ull *b1c, *b2c, *b1f, *b2f;
    int *idx_c, *idx_f;
    cudaGetSymbolAddress((void**)&nsq_c, g_nsq_c);
    cudaGetSymbolAddress((void**)&nsq_f, g_nsq_f);
    cudaGetSymbolAddress((void**)&xnsq_c, g_xnsq_c);
    cudaGetSymbolAddress((void**)&xnsq_f, g_xnsq_f);
    cudaGetSymbolAddress((void**)&b1c, g_b1c);
    cudaGetSymbolAddress((void**)&b2c, g_b2c);
    cudaGetSymbolAddress((void**)&b1f, g_b1f);
    cudaGetSymbolAddress((void**)&b2f, g_b2f);
    cudaGetSymbolAddress((void**)&idx_c, g_idx_c);
    cudaGetSymbolAddress((void**)&idx_f, g_idx_f);
    cudaGetSymbolAddress((void**)&qc, g_qc);
    cudaGetSymbolAddress((void**)&qf, g_qf);
    cudaGetSymbolAddress((void**)&res, g_res);
    cudaGetSymbolAddress((void**)&h, g_h);

    cudaFuncSetAttribute(mma_gemm<0>, cudaFuncAttributeMaxDynamicSharedMemorySize, SMEM_DYN);
    cudaFuncSetAttribute(mma_gemm<1>, cudaFuncAttributeMaxDynamicSharedMemorySize, SMEM_DYN);

    prep_kernel<<<(CB + FB + NROWS) * 32 / 256, 256>>>(z, ce, fe);
    mma_gemm<0><<<dim3(NROWS / BM, CB / BN), 256, SMEM_DYN>>>(z, 1024, ce, nsq_c, xnsq_c, b1c, b2c, nullptr);
    fixup_kernel<<<NROWS, 256>>>(z, 1024, ce, CB, nsq_c, xnsq_c, b1c, b2c, idx_c);
    gather_loss<<<NROWS, 256>>>(ce, idx_c, z, 1024, qc);
    mma_gemm<1><<<dim3(NROWS / BM, D / BN), 256, SMEM_DYN>>>(qc, D, w_c2f, b_c2f, nullptr, nullptr, nullptr, h);
    ln_kernel<0><<<NROWS, 512>>>(h, g_c2f, be_c2f, z, gc_raw, gf_raw, nullptr);
    mma_gemm<0><<<dim3(NROWS / BM, FB / BN), 256, SMEM_DYN>>>(res, D, fe, nsq_f, xnsq_f, b1f, b2f, nullptr);
    fixup_kernel<<<NROWS, 256>>>(res, D, fe, FB, nsq_f, xnsq_f, b1f, b2f, idx_f);
    gather_loss<<<NROWS, 256>>>(fe, idx_f, res, D, qf);
    mma_gemm<1><<<dim3(NROWS / BM, D / BN), 256, SMEM_DYN>>>(qf, D, w_f2c, b_f2c, nullptr, nullptr, nullptr, h);
    ln_kernel<1><<<NROWS, 512>>>(h, g_f2c, be_f2c, z, gc_raw, gf_raw, out);
}

// round 7
// speedup vs baseline: 1.9019x; 1.9019x over previous
#include <cuda_runtime.h>
#include <cuda_fp16.h>
#include <cstdint>
#include <math.h>

#define NROWS 8192
#define D     512
#define CB    4096
#define FB    8192
#define BM    128
#define BN    128
#define KC    64
#define NCH   (D / KC)
#define THRESH 2e-4f
#define SMEM_DYN 65536

typedef unsigned long long ull;

// -------------------- device scratch --------------------
__device__ float g_nsq_c[CB], g_nsq_f[FB];
__device__ float g_xnsq_c[NROWS], g_xnsq_f[NROWS];
__device__ ull   g_b1c[NROWS], g_b2c[NROWS], g_b1f[NROWS], g_b2f[NROWS];
__device__ ull   g_exc[NROWS], g_exf[NROWS];
__device__ int   g_idx_c[NROWS], g_idx_f[NROWS];
__device__ int   g_list_c[NROWS], g_list_f[NROWS];
__device__ int   g_cnt_c, g_cnt_f;
__device__ float g_qc[NROWS * D], g_qf[NROWS * D];
__device__ float g_ci[NROWS * D], g_res[NROWS * D], g_h[NROWS * D];
__device__ __half g_zc_h[NROWS * D], g_zc_l[NROWS * D];
__device__ __half g_ce_h[CB * D],   g_ce_l[CB * D];
__device__ __half g_fe_h[FB * D],   g_fe_l[FB * D];
__device__ __half g_res_h[NROWS * D], g_res_l[NROWS * D];
__device__ __half g_q_h[NROWS * D],   g_q_l[NROWS * D];
__device__ __half g_w1_h[D * D], g_w1_l[D * D], g_w2_h[D * D], g_w2_l[D * D];
__device__ float g_loss;

// -------------------- helpers --------------------
__device__ __forceinline__ uint32_t smem_u32(const void* p) {
    uint32_t a;
    asm("{ .reg .u64 t; cvta.to.shared.u64 t, %1; cvt.u32.u64 %0, t; }" : "=r"(a) : "l"(p));
    return a;
}
#define SWZ(o) ((o) ^ (((o) >> 3) & 0x70))
#define LDM4(r0, r1, r2, r3, a) \
    asm volatile("ldmatrix.sync.aligned.m8n8.x4.shared.b16 {%0,%1,%2,%3}, [%4];" \
        : "=r"(r0), "=r"(r1), "=r"(r2), "=r"(r3) : "r"(a))
#define MMA_F16(c, a, b) \
    asm volatile("mma.sync.aligned.m16n8k16.row.col.f32.f16.f16.f32 " \
        "{%0,%1,%2,%3}, {%4,%5,%6,%7}, {%8,%9}, {%0,%1,%2,%3};" \
        : "+f"((c)[0]), "+f"((c)[1]), "+f"((c)[2]), "+f"((c)[3]) \
        : "r"((a)[0]), "r"((a)[1]), "r"((a)[2]), "r"((a)[3]), "r"((b)[0]), "r"((b)[1]))

__device__ __forceinline__ ull packdi(float d, unsigned j) {
    unsigned u = __float_as_uint(d);
    u = (u & 0x80000000u) ? ~u : (u | 0x80000000u);
    return ((ull)u << 32) | (ull)j;
}
__device__ __forceinline__ float unpackd(ull p) {
    unsigned u = (unsigned)(p >> 32);
    u = (u & 0x80000000u) ? (u & 0x7fffffffu) : ~u;
    return __uint_as_float(u);
}
__device__ __forceinline__ void top2ins(ull& m1, ull& m2, ull p) {
    if (p < m1) { m2 = m1; m1 = p; }
    else if (p < m2) m2 = p;
}

// -------------------- prep: norms + init --------------------
__global__ void prep_kernel(const float* __restrict__ z,
                            const float* __restrict__ ce, const float* __restrict__ fe) {
    int tid = blockIdx.x * blockDim.x + threadIdx.x;
    int w = tid >> 5, lane = tid & 31;
    if (w < CB + FB + NROWS) {
        const float* src;
        if (w < CB)           src = ce + (size_t)w * D;
        else if (w < CB + FB) src = fe + (size_t)(w - CB) * D;
        else                  src = z + (size_t)(w - CB - FB) * 1024;
        float s = 0.f;
        #pragma unroll
        for (int it = 0; it < 4; it++) {
            float4 v = *(const float4*)(src + lane * 4 + it * 128);
            s += v.x * v.x + v.y * v.y + v.z * v.z + v.w * v.w;
        }
        #pragma unroll
        for (int o = 16; o; o >>= 1) s += __shfl_xor_sync(0xffffffffu, s, o);
        if (lane == 0) {
            if (w < CB)           g_nsq_c[w] = s;
            else if (w < CB + FB) g_nsq_f[w - CB] = s;
            else                  g_xnsq_c[w - CB - FB] = s;
        }
    }
    if (tid < NROWS) {
        g_b1c[tid] = ~0ull; g_b2c[tid] = ~0ull;
        g_b1f[tid] = ~0ull; g_b2f[tid] = ~0ull;
        g_exc[tid] = ~0ull; g_exf[tid] = ~0ull;
    }
    if (tid == 0) { g_loss = 0.f; g_cnt_c = 0; g_cnt_f = 0; }
}

// -------------------- fp32 -> fp16 hi/lo split --------------------
__global__ void split_kernel(const float* __restrict__ src, int ld, int nrows,
                             __half* __restrict__ hi, __half* __restrict__ lo) {
    int idx = blockIdx.x * blockDim.x + threadIdx.x;
    int tot = nrows * (D / 4);
    if (idx >= tot) return;
    int r = idx / (D / 4), c = (idx % (D / 4)) * 4;
    float4 v = *(const float4*)(src + (size_t)r * ld + c);
    __half hs[4], ls[4];
    hs[0] = __float2half_rn(v.x); ls[0] = __float2half_rn(v.x - __half2float(hs[0]));
    hs[1] = __float2half_rn(v.y); ls[1] = __float2half_rn(v.y - __half2float(hs[1]));
    hs[2] = __float2half_rn(v.z); ls[2] = __float2half_rn(v.z - __half2float(hs[2]));
    hs[3] = __float2half_rn(v.w); ls[3] = __float2half_rn(v.w - __half2float(hs[3]));
    *(uint2*)(hi + (size_t)r * D + c) = *(uint2*)hs;
    *(uint2*)(lo + (size_t)r * D + c) = *(uint2*)ls;
}

// -------------------- HMMA fp16 3-pass GEMM (pre-split operands) --------------------
// MODE 0: VQ top-2 of d = fl(fl(xx+ee) - 2*dot) ; MODE 1: out = dot + bias
template <int MODE>
__global__ __launch_bounds__(256, 2) void mma_gemm(
    const __half* __restrict__ Ah, const __half* __restrict__ Al,
    const __half* __restrict__ Bh, const __half* __restrict__ Bl,
    const float* __restrict__ aux, const float* __restrict__ xnsq,
    ull* __restrict__ best1, ull* __restrict__ best2,
    float* __restrict__ out)
{
    extern __shared__ char sm[];
    __shared__ ull sb1[BM], sb2[BM];
    const int t = threadIdx.x;
    const int lane = t & 31, wid = t >> 5;
    const int warp_m = wid & 1, warp_n = wid >> 1;
    const int row0 = blockIdx.x * BM, col0 = blockIdx.y * BN;
    const uint32_t smb = smem_u32(sm);
    const uint32_t AHs = smb, ALs = smb + 16384u, BHs = smb + 32768u, BLs = smb + 49152u;

    if (MODE == 0 && t < BM) { sb1[t] = ~0ull; sb2[t] = ~0ull; }

    float acc[4][4][4];
    #pragma unroll
    for (int i = 0; i < 4; i++)
        #pragma unroll
        for (int j = 0; j < 4; j++)
            #pragma unroll
            for (int k = 0; k < 4; k++) acc[i][j][k] = 0.f;

    const int lrow = t >> 1, lseg = t & 1;
    const size_t aoff = (size_t)(row0 + lrow) * D + lseg * 32;
    const size_t boff = (size_t)(col0 + lrow) * D + lseg * 32;
    const uint32_t stb = (uint32_t)(lrow * 128 + lseg * 64);

    #pragma unroll 1
    for (int c = 0; c < NCH; c++) {
        const int kb = c * KC;
        #pragma unroll
        for (int it = 0; it < 4; it++) {
            const uint32_t so = SWZ(stb + it * 16);
            *(uint4*)(sm + so)           = *(const uint4*)(Ah + aoff + kb + it * 8);
            *(uint4*)(sm + 16384u + so)  = *(const uint4*)(Al + aoff + kb + it * 8);
            *(uint4*)(sm + 32768u + so)  = *(const uint4*)(Bh + boff + kb + it * 8);
            *(uint4*)(sm + 49152u + so)  = *(const uint4*)(Bl + boff + kb + it * 8);
        }
        __syncthreads();
        #pragma unroll
        for (int k16 = 0; k16 < 4; k16++) {
            uint32_t bhf[4][2], blf[4][2];
            #pragma unroll
            for (int nt2 = 0; nt2 < 2; nt2++) {
                int nrow = warp_n * 32 + nt2 * 16 + (lane & 7) + ((lane & 16) ? 8 : 0);
                int kbyte = k16 * 32 + ((lane >> 3) & 1) * 16;
                uint32_t off = SWZ((uint32_t)(nrow * 128 + kbyte));
                LDM4(bhf[nt2 * 2][0], bhf[nt2 * 2][1], bhf[nt2 * 2 + 1][0], bhf[nt2 * 2 + 1][1], BHs + off);
                LDM4(blf[nt2 * 2][0], blf[nt2 * 2][1], blf[nt2 * 2 + 1][0], blf[nt2 * 2 + 1][1], BLs + off);
            }
            #pragma unroll
            for (int mt = 0; mt < 4; mt++) {
                int mrow = warp_m * 64 + mt * 16 + (lane & 15);
                int kbyte = k16 * 32 + (lane >> 4) * 16;
                uint32_t off = SWZ((uint32_t)(mrow * 128 + kbyte));
                uint32_t ah[4], al[4];
                LDM4(ah[0], ah[1], ah[2], ah[3], AHs + off);
                #pragma unroll
                for (int nt = 0; nt < 4; nt++) MMA_F16(acc[mt][nt], ah, bhf[nt]);
                #pragma unroll
                for (int nt = 0; nt < 4; nt++) MMA_F16(acc[mt][nt], ah, blf[nt]);
                LDM4(al[0], al[1], al[2], al[3], ALs + off);
                #pragma unroll
                for (int nt = 0; nt < 4; nt++) MMA_F16(acc[mt][nt], al, bhf[nt]);
            }
        }
        __syncthreads();
    }

    const int g = lane >> 2, tg = lane & 3;
    if (MODE == 0) {
        #pragma unroll
        for (int mt = 0; mt < 4; mt++) {
            #pragma unroll
            for (int h8 = 0; h8 < 2; h8++) {
                int lrow2 = warp_m * 64 + mt * 16 + g + h8 * 8;
                float xx = xnsq[row0 + lrow2];
                ull m1 = ~0ull, m2 = ~0ull;
                #pragma unroll
                for (int nt = 0; nt < 4; nt++) {
                    int colg = col0 + warp_n * 32 + nt * 8 + tg * 2;
                    float d0 = __fadd_rn(__fadd_rn(xx, aux[colg]), -2.f * acc[mt][nt][h8 * 2 + 0]);
                    float d1 = __fadd_rn(__fadd_rn(xx, aux[colg + 1]), -2.f * acc[mt][nt][h8 * 2 + 1]);
                    top2ins(m1, m2, packdi(d0, (unsigned)colg));
                    top2ins(m1, m2, packdi(d1, (unsigned)(colg + 1)));
                }
                #pragma unroll
                for (int o = 1; o <= 2; o <<= 1) {
                    ull o1 = __shfl_xor_sync(0xffffffffu, m1, o);
                    ull o2 = __shfl_xor_sync(0xffffffffu, m2, o);
                    ull n1 = o1 < m1 ? o1 : m1;
                    ull hi = o1 > m1 ? o1 : m1;
                    ull lo2 = o2 < m2 ? o2 : m2;
                    m2 = hi < lo2 ? hi : lo2;
                    m1 = n1;
                }
                if (tg == 0) {
                    ull old = atomicMin(&sb1[lrow2], m1);
                    atomicMin(&sb2[lrow2], old > m1 ? old : m1);
                    atomicMin(&sb2[lrow2], m2);
                }
            }
        }
        __syncthreads();
        if (t < BM) {
            ull s1 = sb1[t], s2 = sb2[t];
            ull old = atomicMin(&best1[row0 + t], s1);
            atomicMin(&best2[row0 + t], old > s1 ? old : s1);
            atomicMin(&best2[row0 + t], s2);
        }
    } else {
        #pragma unroll
        for (int mt = 0; mt < 4; mt++) {
            #pragma unroll
            for (int h8 = 0; h8 < 2; h8++) {
                int row = row0 + warp_m * 64 + mt * 16 + g + h8 * 8;
                #pragma unroll
                for (int nt = 0; nt < 4; nt++) {
                    int colg = col0 + warp_n * 32 + nt * 8 + tg * 2;
                    float2 o2 = make_float2(acc[mt][nt][h8 * 2 + 0] + aux[colg],
                                            acc[mt][nt][h8 * 2 + 1] + aux[colg + 1]);
                    *(float2*)&out[(size_t)row * D + colg] = o2;
                }
            }
        }
    }
}

// -------------------- flag: compact near-tie rows --------------------
__global__ void flag_kernel(const ull* __restrict__ b1, const ull* __restrict__ b2,
                            int* __restrict__ idx, int* __restrict__ list, int* __restrict__ cnt) {
    int r = blockIdx.x * blockDim.x + threadIdx.x;
    if (r >= NROWS) return;
    ull p1 = b1[r];
    idx[r] = (int)(p1 & 0xffffffffu);
    if (unpackd(b2[r]) - unpackd(p1) <= THRESH) {
        int pos = atomicAdd(cnt, 1);
        list[pos] = r;
    }
}

// -------------------- exact re-decide (emb-tiled over flagged rows) --------------------
__global__ void exact_kernel(const float* __restrict__ x, int ldx,
                             const float* __restrict__ emb,
                             const float* __restrict__ nsq, const float* __restrict__ xnsq,
                             const int* __restrict__ list, const int* __restrict__ cnt,
                             ull* __restrict__ ex) {
    __shared__ float es[16 * 512];
    __shared__ float xs[512];
    const int t = threadIdx.x, lane = t & 31, w = t >> 5;
    const float* ep = emb + (size_t)blockIdx.x * 16 * 512;
    for (int i = t; i < 16 * 512 / 4; i += 256) ((float4*)es)[i] = ((const float4*)ep)[i];
    int n = *cnt;
    for (int i = 0; i < n; i++) {
        int r = list[i];
        __syncthreads();
        if (t < 128) ((float4*)xs)[t] = *(const float4*)(x + (size_t)r * ldx + t * 4);
        __syncthreads();
        float xx = xnsq[r];
        #pragma unroll
        for (int e2 = 0; e2 < 2; e2++) {
            int j = w * 2 + e2;
            const float* er = es + j * 512;
            float s = 0.f;
            for (int k = lane; k < 512; k += 32) s = fmaf(er[k], xs[k], s);
            #pragma unroll
            for (int o = 16; o; o >>= 1) s += __shfl_xor_sync(0xffffffffu, s, o);
            if (lane == 0) {
                int jg = blockIdx.x * 16 + j;
                float d = __fadd_rn(__fadd_rn(xx, nsq[jg]), -2.f * s);
                atomicMin(ex + r, packdi(d, (unsigned)jg));
            }
        }
    }
}

// -------------------- select exact winners --------------------
__global__ void sel_kernel(const int* __restrict__ list, const int* __restrict__ cnt,
                           const ull* __restrict__ ex, int* __restrict__ idx) {
    int i = blockIdx.x * blockDim.x + threadIdx.x;
    if (i < *cnt) { int r = list[i]; idx[r] = (int)(ex[r] & 0xffffffffu); }
}

// -------------------- gather q = emb[idx] (+ split), loss --------------------
__global__ void gather_loss(const float* __restrict__ emb, const int* __restrict__ idx,
                            const float* __restrict__ x, int ldx, float* __restrict__ q,
                            __half* __restrict__ qh, __half* __restrict__ ql) {
    int r = blockIdx.x;
    int j = idx[r];
    const float* e = emb + (size_t)j * D;
    const float* xr = x + (size_t)r * ldx;
    float* qr = q + (size_t)r * D;
    float ls = 0.f;
    for (int k = threadIdx.x; k < D; k += blockDim.x) {
        float ev = e[k];
        qr[k] = ev;
        __half hh = __float2half_rn(ev);
        qh[(size_t)r * D + k] = hh;
        ql[(size_t)r * D + k] = __float2half_rn(ev - __half2float(hh));
        float dd = ev - xr[k];
        ls += dd * dd;
    }
    #pragma unroll
    for (int o = 16; o; o >>= 1) ls += __shfl_xor_sync(0xffffffffu, ls, o);
    __shared__ float ws[8];
    int w = threadIdx.x >> 5;
    if ((threadIdx.x & 31) == 0) ws[w] = ls;
    __syncthreads();
    if (threadIdx.x == 0) {
        float s = 0.f;
        for (int i = 0; i < 8; i++) s += ws[i];
        atomicAdd(&g_loss, s);
    }
}

// -------------------- LayerNorm + leakyReLU + fused follow-up --------------------
template <int MODE>
__global__ void ln_kernel(const float* __restrict__ h,
                          const float* __restrict__ g, const float* __restrict__ be,
                          const float* __restrict__ z,
                          const float* __restrict__ gc_raw, const float* __restrict__ gf_raw,
                          float* __restrict__ out)
{
    int r = blockIdx.x;
    int j = threadIdx.x;
    float hv = h[(size_t)r * D + j];
    float s = hv, sq = hv * hv;
    #pragma unroll
    for (int o = 16; o; o >>= 1) {
        s += __shfl_xor_sync(0xffffffffu, s, o);
        sq += __shfl_xor_sync(0xffffffffu, sq, o);
    }
    __shared__ float s1[16], s2[16];
    int w = j >> 5, lane = j & 31;
    if (lane == 0) { s1[w] = s; s2[w] = sq; }
    __syncthreads();
    if (w == 0) {
        s = (lane < 16) ? s1[lane] : 0.f;
        sq = (lane < 16) ? s2[lane] : 0.f;
        #pragma unroll
        for (int o = 8; o; o >>= 1) {
            s += __shfl_xor_sync(0xffffffffu, s, o);
            sq += __shfl_xor_sync(0xffffffffu, sq, o);
        }
        if (lane == 0) { s1[0] = s; s2[0] = sq; }
    }
    __syncthreads();
    float mean = s1[0] * (1.f / D);
    float var = s2[0] * (1.f / D) - mean * mean;
    float y = (hv - mean) * rsqrtf(var + 1e-5f) * g[j] + be[j];
    float act = y > 0.f ? y : 0.1f * y;
    float gcv = 1.f / (1.f + expf(-gc_raw[0]));

    if (MODE == 0) {
        float rv = z[(size_t)r * 1024 + D + j] - gcv * act;
        g_ci[(size_t)r * D + j] = act;
        g_res[(size_t)r * D + j] = rv;
        __half hh = __float2half_rn(rv);
        g_res_h[(size_t)r * D + j] = hh;
        g_res_l[(size_t)r * D + j] = __float2half_rn(rv - __half2float(hh));
        float rq = rv * rv;
        #pragma unroll
        for (int o = 16; o; o >>= 1) rq += __shfl_xor_sync(0xffffffffu, rq, o);
        __syncthreads();
        if (lane == 0) s1[w] = rq;
        __syncthreads();
        if (j == 0) {
            float tt = 0.f;
            #pragma unroll
            for (int i = 0; i < 16; i++) tt += s1[i];
            g_xnsq_f[r] = tt;
        }
    } else {
        float gfv = 1.f / (1.f + expf(-gf_raw[0]));
        out[(size_t)r * 1024 + j] = g_qc[(size_t)r * D + j] + 0.1f * gfv * act;
        out[(size_t)r * 1024 + D + j] = g_qf[(size_t)r * D + j] + gcv * g_ci[(size_t)r * D + j];
        if (r == 0 && j == 0)
            out[(size_t)NROWS * 1024] = 1.25f * g_loss / (float)((size_t)NROWS * D);
    }
}

// -------------------- launch --------------------
#define SYMADDR(p, s) cudaGetSymbolAddress((void**)&p, s)

extern "C" void kernel_launch(void* const* d_in, const int* in_sizes, int n_in,
                              void* d_out, int out_size) {
    const float* z      = (const float*)d_in[0];
    const float* ce     = (const float*)d_in[1];
    const float* fe     = (const float*)d_in[2];
    const float* w_c2f  = (const float*)d_in[3];
    const float* b_c2f  = (const float*)d_in[4];
    const float* g_c2f  = (const float*)d_in[5];
    const float* be_c2f = (const float*)d_in[6];
    const float* w_f2c  = (const float*)d_in[7];
    const float* b_f2c  = (const float*)d_in[8];
    const float* g_f2c  = (const float*)d_in[9];
    const float* be_f2c = (const float*)d_in[10];
    const float* gc_raw = (const float*)d_in[11];
    const float* gf_raw = (const float*)d_in[12];
    float* out = (float*)d_out;

    float *nsq_c, *nsq_f, *xnsq_c, *xnsq_f, *qc, *qf, *res, *h;
    ull *b1c, *b2c, *b1f, *b2f, *exc, *exf;
    int *idx_c, *idx_f, *list_c, *list_f, *cnt_c, *cnt_f;
    __half *zc_h, *zc_l, *ce_h, *ce_l, *fe_h, *fe_l, *res_h, *res_l, *q_h, *q_l;
    __half *w1_h, *w1_l, *w2_h, *w2_l;
    SYMADDR(nsq_c, g_nsq_c);   SYMADDR(nsq_f, g_nsq_f);
    SYMADDR(xnsq_c, g_xnsq_c); SYMADDR(xnsq_f, g_xnsq_f);
    SYMADDR(b1c, g_b1c); SYMADDR(b2c, g_b2c); SYMADDR(b1f, g_b1f); SYMADDR(b2f, g_b2f);
    SYMADDR(exc, g_exc); SYMADDR(exf, g_exf);
    SYMADDR(idx_c, g_idx_c); SYMADDR(idx_f, g_idx_f);
    SYMADDR(list_c, g_list_c); SYMADDR(list_f, g_list_f);
    SYMADDR(cnt_c, g_cnt_c); SYMADDR(cnt_f, g_cnt_f);
    SYMADDR(qc, g_qc); SYMADDR(qf, g_qf); SYMADDR(res, g_res); SYMADDR(h, g_h);
    SYMADDR(zc_h, g_zc_h); SYMADDR(zc_l, g_zc_l);
    SYMADDR(ce_h, g_ce_h); SYMADDR(ce_l, g_ce_l);
    SYMADDR(fe_h, g_fe_h); SYMADDR(fe_l, g_fe_l);
    SYMADDR(res_h, g_res_h); SYMADDR(res_l, g_res_l);
    SYMADDR(q_h, g_q_h); SYMADDR(q_l, g_q_l);
    SYMADDR(w1_h, g_w1_h); SYMADDR(w1_l, g_w1_l);
    SYMADDR(w2_h, g_w2_h); SYMADDR(w2_l, g_w2_l);

    cudaFuncSetAttribute(mma_gemm<0>, cudaFuncAttributeMaxDynamicSharedMemorySize, SMEM_DYN);
    cudaFuncSetAttribute(mma_gemm<1>, cudaFuncAttributeMaxDynamicSharedMemorySize, SMEM_DYN);

    prep_kernel<<<(CB + FB + NROWS) * 32 / 256, 256>>>(z, ce, fe);
    split_kernel<<<CB * 128 / 256, 256>>>(ce, D, CB, ce_h, ce_l);
    split_kernel<<<FB * 128 / 256, 256>>>(fe, D, FB, fe_h, fe_l);
    split_kernel<<<NROWS * 128 / 256, 256>>>(z, 1024, NROWS, zc_h, zc_l);
    split_kernel<<<D * 128 / 256, 256>>>(w_c2f, D, D, w1_h, w1_l);
    split_kernel<<<D * 128 / 256, 256>>>(w_f2c, D, D, w2_h, w2_l);

    // coarse VQ
    mma_gemm<0><<<dim3(NROWS / BM, CB / BN), 256, SMEM_DYN>>>(zc_h, zc_l, ce_h, ce_l, nsq_c, xnsq_c, b1c, b2c, nullptr);
    flag_kernel<<<NROWS / 256, 256>>>(b1c, b2c, idx_c, list_c, cnt_c);
    exact_kernel<<<CB / 16, 256>>>(z, 1024, ce, nsq_c, xnsq_c, list_c, cnt_c, exc);
    sel_kernel<<<NROWS / 256, 256>>>(list_c, cnt_c, exc, idx_c);
    gather_loss<<<NROWS, 256>>>(ce, idx_c, z, 1024, qc, q_h, q_l);
    // MLP c2f
    mma_gemm<1><<<dim3(NROWS / BM, D / BN), 256, SMEM_DYN>>>(q_h, q_l, w1_h, w1_l, b_c2f, nullptr, nullptr, nullptr, h);
    ln_kernel<0><<<NROWS, 512>>>(h, g_c2f, be_c2f, z, gc_raw, gf_raw, nullptr);
    // fine VQ
    mma_gemm<0><<<dim3(NROWS / BM, FB / BN), 256, SMEM_DYN>>>(res_h, res_l, fe_h, fe_l, nsq_f, xnsq_f, b1f, b2f, nullptr);
    flag_kernel<<<NROWS / 256, 256>>>(b1f, b2f, idx_f, list_f, cnt_f);
    exact_kernel<<<FB / 16, 256>>>(res, D, fe, nsq_f, xnsq_f, list_f, cnt_f, exf);
    sel_kernel<<<NROWS / 256, 256>>>(list_f, cnt_f, exf, idx_f);
    gather_loss<<<NROWS, 256>>>(fe, idx_f, res, D, qf, q_h, q_l);
    // MLP f2c
    mma_gemm<1><<<dim3(NROWS / BM, D / BN), 256, SMEM_DYN>>>(q_h, q_l, w2_h, w2_l, b_f2c, nullptr, nullptr, nullptr, h);
    ln_kernel<1><<<NROWS, 512>>>(h, g_f2c, be_f2c, z, gc_raw, gf_raw, out);
}

// round 8
// speedup vs baseline: 2.3460x; 1.2335x over previous
#include <cuda_runtime.h>
#include <cuda_fp16.h>
#include <cstdint>
#include <math.h>

#define NROWS 8192
#define D     512
#define CB    4096
#define FB    8192
#define BM    128
#define BN    128
#define KC    32
#define NCH   (D / KC)
#define THRESH 1e-4f
#define SMEM_DYN 65536

typedef unsigned long long ull;

// -------------------- device scratch --------------------
__device__ float g_nsq_c[CB], g_nsq_f[FB];
__device__ float g_xnsq_c[NROWS], g_xnsq_f[NROWS];
__device__ ull   g_b1c[NROWS], g_b2c[NROWS], g_b1f[NROWS], g_b2f[NROWS];
__device__ ull   g_exc[NROWS], g_exf[NROWS];
__device__ int   g_idx_c[NROWS], g_idx_f[NROWS];
__device__ int   g_list_c[NROWS], g_list_f[NROWS];
__device__ int   g_cnt_c, g_cnt_f;
__device__ float g_qc[NROWS * D], g_qf[NROWS * D];
__device__ float g_ci[NROWS * D], g_res[NROWS * D], g_h[NROWS * D];
__device__ __half g_zc_h[NROWS * D], g_zc_l[NROWS * D];
__device__ __half g_ce_h[CB * D],   g_ce_l[CB * D];
__device__ __half g_fe_h[FB * D],   g_fe_l[FB * D];
__device__ __half g_res_h[NROWS * D], g_res_l[NROWS * D];
__device__ __half g_q_h[NROWS * D],   g_q_l[NROWS * D];
__device__ __half g_w1_h[D * D], g_w1_l[D * D], g_w2_h[D * D], g_w2_l[D * D];
__device__ float g_loss;

// -------------------- helpers --------------------
__device__ __forceinline__ uint32_t smem_u32(const void* p) {
    uint32_t a;
    asm("{ .reg .u64 t; cvta.to.shared.u64 t, %1; cvt.u32.u64 %0, t; }" : "=r"(a) : "l"(p));
    return a;
}
// 64B-row swizzle: XOR 16B-segment bits [5:4] with row bits (o[8:7])
#define SWZ32(o) ((o) ^ (((o) >> 3) & 0x30))
#define LDM4(r0, r1, r2, r3, a) \
    asm volatile("ldmatrix.sync.aligned.m8n8.x4.shared.b16 {%0,%1,%2,%3}, [%4];" \
        : "=r"(r0), "=r"(r1), "=r"(r2), "=r"(r3) : "r"(a))
#define MMA_F16(c, a, b) \
    asm volatile("mma.sync.aligned.m16n8k16.row.col.f32.f16.f16.f32 " \
        "{%0,%1,%2,%3}, {%4,%5,%6,%7}, {%8,%9}, {%0,%1,%2,%3};" \
        : "+f"((c)[0]), "+f"((c)[1]), "+f"((c)[2]), "+f"((c)[3]) \
        : "r"((a)[0]), "r"((a)[1]), "r"((a)[2]), "r"((a)[3]), "r"((b)[0]), "r"((b)[1]))
#define CP_ASYNC16(dst, src) \
    asm volatile("cp.async.cg.shared.global [%0], [%1], 16;" :: "r"(dst), "l"(src))
#define CP_COMMIT() asm volatile("cp.async.commit_group;")
#define CP_WAIT1()  asm volatile("cp.async.wait_group 1;")

__device__ __forceinline__ ull packdi(float d, unsigned j) {
    unsigned u = __float_as_uint(d);
    u = (u & 0x80000000u) ? ~u : (u | 0x80000000u);
    return ((ull)u << 32) | (ull)j;
}
__device__ __forceinline__ float unpackd(ull p) {
    unsigned u = (unsigned)(p >> 32);
    u = (u & 0x80000000u) ? (u & 0x7fffffffu) : ~u;
    return __uint_as_float(u);
}
__device__ __forceinline__ void top2ins(ull& m1, ull& m2, ull p) {
    if (p < m1) { m2 = m1; m1 = p; }
    else if (p < m2) m2 = p;
}

// -------------------- launch 1: init best arrays --------------------
__global__ void init_kernel() {
    int r = blockIdx.x * blockDim.x + threadIdx.x;
    if (r < NROWS) {
        g_b1c[r] = ~0ull; g_b2c[r] = ~0ull;
        g_b1f[r] = ~0ull; g_b2f[r] = ~0ull;
        g_exc[r] = ~0ull; g_exf[r] = ~0ull;
    }
}
// -------------------- launch 2: zero scalars --------------------
__global__ void zero_kernel() {
    if (threadIdx.x == 0) { g_loss = 0.f; g_cnt_c = 0; g_cnt_f = 0; }
}

// -------------------- launch 3: fused norms + fp16 hi/lo splits --------------------
__global__ void prep_split(const float* __restrict__ z,
                           const float* __restrict__ ce, const float* __restrict__ fe,
                           const float* __restrict__ w1, const float* __restrict__ w2) {
    int gw = (blockIdx.x * blockDim.x + threadIdx.x) >> 5;
    int lane = threadIdx.x & 31;
    const float* src;
    __half *hi, *lo;
    float* nrm = nullptr;
    if (gw < CB) {
        src = ce + (size_t)gw * D; hi = g_ce_h + (size_t)gw * D; lo = g_ce_l + (size_t)gw * D;
        nrm = g_nsq_c + gw;
    } else if (gw < CB + FB) {
        int r = gw - CB;
        src = fe + (size_t)r * D; hi = g_fe_h + (size_t)r * D; lo = g_fe_l + (size_t)r * D;
        nrm = g_nsq_f + r;
    } else if (gw < CB + FB + NROWS) {
        int r = gw - CB - FB;
        src = z + (size_t)r * 1024; hi = g_zc_h + (size_t)r * D; lo = g_zc_l + (size_t)r * D;
        nrm = g_xnsq_c + r;
    } else if (gw < CB + FB + NROWS + D) {
        int r = gw - CB - FB - NROWS;
        src = w1 + (size_t)r * D; hi = g_w1_h + (size_t)r * D; lo = g_w1_l + (size_t)r * D;
    } else if (gw < CB + FB + NROWS + 2 * D) {
        int r = gw - CB - FB - NROWS - D;
        src = w2 + (size_t)r * D; hi = g_w2_h + (size_t)r * D; lo = g_w2_l + (size_t)r * D;
    } else return;

    float s = 0.f;
    #pragma unroll
    for (int it = 0; it < 4; it++) {
        int c = lane * 4 + it * 128;
        float4 v = *(const float4*)(src + c);
        s += v.x * v.x + v.y * v.y + v.z * v.z + v.w * v.w;
        __half hs[4], ls[4];
        hs[0] = __float2half_rn(v.x); ls[0] = __float2half_rn(v.x - __half2float(hs[0]));
        hs[1] = __float2half_rn(v.y); ls[1] = __float2half_rn(v.y - __half2float(hs[1]));
        hs[2] = __float2half_rn(v.z); ls[2] = __float2half_rn(v.z - __half2float(hs[2]));
        hs[3] = __float2half_rn(v.w); ls[3] = __float2half_rn(v.w - __half2float(hs[3]));
        *(uint2*)(hi + c) = *(uint2*)hs;
        *(uint2*)(lo + c) = *(uint2*)ls;
    }
    if (nrm) {
        #pragma unroll
        for (int o = 16; o; o >>= 1) s += __shfl_xor_sync(0xffffffffu, s, o);
        if (lane == 0) *nrm = s;
    }
}

// -------------------- HMMA fp16 3-pass GEMM, cp.async double-buffered --------------------
// MODE 0: VQ top-2 of d = fl(fl(xx+ee) - 2*dot) ; MODE 1: out = dot + bias
template <int MODE>
__global__ __launch_bounds__(256, 2) void mma_gemm(
    const __half* __restrict__ Ah, const __half* __restrict__ Al,
    const __half* __restrict__ Bh, const __half* __restrict__ Bl,
    const float* __restrict__ aux, const float* __restrict__ xnsq,
    ull* __restrict__ best1, ull* __restrict__ best2,
    float* __restrict__ out)
{
    extern __shared__ char sm[];
    __shared__ ull sb1[BM], sb2[BM];
    const int t = threadIdx.x;
    const int lane = t & 31, wid = t >> 5;
    const int warp_m = wid & 1, warp_n = wid >> 1;
    const int row0 = blockIdx.x * BM, col0 = blockIdx.y * BN;
    const uint32_t smb = smem_u32(sm);

    if (MODE == 0 && t < BM) { sb1[t] = ~0ull; sb2[t] = ~0ull; }

    float acc[4][4][4];
    #pragma unroll
    for (int i = 0; i < 4; i++)
        #pragma unroll
        for (int j = 0; j < 4; j++)
            #pragma unroll
            for (int k = 0; k < 4; k++) acc[i][j][k] = 0.f;

    // per-thread load mapping: row = t>>1, half (of the 32 halves) = t&1
    const int lrow = t >> 1, lh = t & 1;
    const size_t aoff = (size_t)(row0 + lrow) * D + lh * 16;
    const size_t boff = (size_t)(col0 + lrow) * D + lh * 16;
    const uint32_t st0 = SWZ32((uint32_t)(lrow * 64 + lh * 32));
    const uint32_t st1 = SWZ32((uint32_t)(lrow * 64 + lh * 32 + 16));

    // buffer b at smb + b*32768; arrays AH +0, AL +8192, BH +16384, BL +24576
    #define ISSUE(c) do { \
        uint32_t bb = smb + ((c) & 1) * 32768u; \
        const int kb = (c) * KC; \
        CP_ASYNC16(bb + st0,           (const char*)(Ah + aoff + kb)); \
        CP_ASYNC16(bb + st1,           (const char*)(Ah + aoff + kb + 8)); \
        CP_ASYNC16(bb + 8192u  + st0,  (const char*)(Al + aoff + kb)); \
        CP_ASYNC16(bb + 8192u  + st1,  (const char*)(Al + aoff + kb + 8)); \
        CP_ASYNC16(bb + 16384u + st0,  (const char*)(Bh + boff + kb)); \
        CP_ASYNC16(bb + 16384u + st1,  (const char*)(Bh + boff + kb + 8)); \
        CP_ASYNC16(bb + 24576u + st0,  (const char*)(Bl + boff + kb)); \
        CP_ASYNC16(bb + 24576u + st1,  (const char*)(Bl + boff + kb + 8)); \
        CP_COMMIT(); \
    } while (0)

    ISSUE(0);
    ISSUE(1);

    #pragma unroll 1
    for (int c = 0; c < NCH; c++) {
        const uint32_t bb = smb + (c & 1) * 32768u;
        const uint32_t AHs = bb, ALs = bb + 8192u, BHs = bb + 16384u, BLs = bb + 24576u;
        CP_WAIT1();
        __syncthreads();
        #pragma unroll
        for (int k16 = 0; k16 < 2; k16++) {
            uint32_t bhf[4][2], blf[4][2];
            #pragma unroll
            for (int nt2 = 0; nt2 < 2; nt2++) {
                int nrow = warp_n * 32 + nt2 * 16 + (lane & 7) + ((lane & 16) ? 8 : 0);
                int kbyte = k16 * 32 + ((lane >> 3) & 1) * 16;
                uint32_t off = SWZ32((uint32_t)(nrow * 64 + kbyte));
                LDM4(bhf[nt2 * 2][0], bhf[nt2 * 2][1], bhf[nt2 * 2 + 1][0], bhf[nt2 * 2 + 1][1], BHs + off);
                LDM4(blf[nt2 * 2][0], blf[nt2 * 2][1], blf[nt2 * 2 + 1][0], blf[nt2 * 2 + 1][1], BLs + off);
            }
            #pragma unroll
            for (int mt = 0; mt < 4; mt++) {
                int mrow = warp_m * 64 + mt * 16 + (lane & 15);
                int kbyte = k16 * 32 + (lane >> 4) * 16;
                uint32_t off = SWZ32((uint32_t)(mrow * 64 + kbyte));
                uint32_t ah[4], al[4];
                LDM4(ah[0], ah[1], ah[2], ah[3], AHs + off);
                #pragma unroll
                for (int nt = 0; nt < 4; nt++) MMA_F16(acc[mt][nt], ah, bhf[nt]);
                #pragma unroll
                for (int nt = 0; nt < 4; nt++) MMA_F16(acc[mt][nt], ah, blf[nt]);
                LDM4(al[0], al[1], al[2], al[3], ALs + off);
                #pragma unroll
                for (int nt = 0; nt < 4; nt++) MMA_F16(acc[mt][nt], al, bhf[nt]);
            }
        }
        __syncthreads();
        if (c + 2 < NCH) { ISSUE(c + 2); } else { CP_COMMIT(); }
    }

    const int g = lane >> 2, tg = lane & 3;
    if (MODE == 0) {
        #pragma unroll
        for (int mt = 0; mt < 4; mt++) {
            #pragma unroll
            for (int h8 = 0; h8 < 2; h8++) {
                int lrow2 = warp_m * 64 + mt * 16 + g + h8 * 8;
                float xx = xnsq[row0 + lrow2];
                ull m1 = ~0ull, m2 = ~0ull;
                #pragma unroll
                for (int nt = 0; nt < 4; nt++) {
                    int colg = col0 + warp_n * 32 + nt * 8 + tg * 2;
                    float d0 = __fadd_rn(__fadd_rn(xx, aux[colg]), -2.f * acc[mt][nt][h8 * 2 + 0]);
                    float d1 = __fadd_rn(__fadd_rn(xx, aux[colg + 1]), -2.f * acc[mt][nt][h8 * 2 + 1]);
                    top2ins(m1, m2, packdi(d0, (unsigned)colg));
                    top2ins(m1, m2, packdi(d1, (unsigned)(colg + 1)));
                }
                #pragma unroll
                for (int o = 1; o <= 2; o <<= 1) {
                    ull o1 = __shfl_xor_sync(0xffffffffu, m1, o);
                    ull o2 = __shfl_xor_sync(0xffffffffu, m2, o);
                    ull n1 = o1 < m1 ? o1 : m1;
                    ull hi = o1 > m1 ? o1 : m1;
                    ull lo2 = o2 < m2 ? o2 : m2;
                    m2 = hi < lo2 ? hi : lo2;
                    m1 = n1;
                }
                if (tg == 0) {
                    ull old = atomicMin(&sb1[lrow2], m1);
                    atomicMin(&sb2[lrow2], old > m1 ? old : m1);
                    atomicMin(&sb2[lrow2], m2);
                }
            }
        }
        __syncthreads();
        if (t < BM) {
            ull s1 = sb1[t], s2 = sb2[t];
            ull old = atomicMin(&best1[row0 + t], s1);
            atomicMin(&best2[row0 + t], old > s1 ? old : s1);
            atomicMin(&best2[row0 + t], s2);
        }
    } else {
        #pragma unroll
        for (int mt = 0; mt < 4; mt++) {
            #pragma unroll
            for (int h8 = 0; h8 < 2; h8++) {
                int row = row0 + warp_m * 64 + mt * 16 + g + h8 * 8;
                #pragma unroll
                for (int nt = 0; nt < 4; nt++) {
                    int colg = col0 + warp_n * 32 + nt * 8 + tg * 2;
                    float2 o2 = make_float2(acc[mt][nt][h8 * 2 + 0] + aux[colg],
                                            acc[mt][nt][h8 * 2 + 1] + aux[colg + 1]);
                    *(float2*)&out[(size_t)row * D + colg] = o2;
                }
            }
        }
    }
    #undef ISSUE
}

// -------------------- flag: compact near-tie rows --------------------
__global__ void flag_kernel(const ull* __restrict__ b1, const ull* __restrict__ b2,
                            int* __restrict__ idx, int* __restrict__ list, int* __restrict__ cnt) {
    int r = blockIdx.x * blockDim.x + threadIdx.x;
    if (r >= NROWS) return;
    ull p1 = b1[r];
    idx[r] = (int)(p1 & 0xffffffffu);
    if (unpackd(b2[r]) - unpackd(p1) <= THRESH) {
        int pos = atomicAdd(cnt, 1);
        list[pos] = r;
    }
}

// -------------------- exact re-decide (emb-tiled over flagged rows) --------------------
__global__ void exact_kernel(const float* __restrict__ x, int ldx,
                             const float* __restrict__ emb,
                             const float* __restrict__ nsq, const float* __restrict__ xnsq,
                             const int* __restrict__ list, const int* __restrict__ cnt,
                             ull* __restrict__ ex) {
    int n = *cnt;
    if (n == 0) return;
    __shared__ float es[16 * 512];
    __shared__ float xs[512];
    const int t = threadIdx.x, lane = t & 31, w = t >> 5;
    const float* ep = emb + (size_t)blockIdx.x * 16 * 512;
    for (int i = t; i < 16 * 512 / 4; i += 256) ((float4*)es)[i] = ((const float4*)ep)[i];
    for (int i = 0; i < n; i++) {
        int r = list[i];
        __syncthreads();
        if (t < 128) ((float4*)xs)[t] = *(const float4*)(x + (size_t)r * ldx + t * 4);
        __syncthreads();
        float xx = xnsq[r];
        #pragma unroll
        for (int e2 = 0; e2 < 2; e2++) {
            int j = w * 2 + e2;
            const float* er = es + j * 512;
            float s = 0.f;
            for (int k = lane; k < 512; k += 32) s = fmaf(er[k], xs[k], s);
            #pragma unroll
            for (int o = 16; o; o >>= 1) s += __shfl_xor_sync(0xffffffffu, s, o);
            if (lane == 0) {
                int jg = blockIdx.x * 16 + j;
                float d = __fadd_rn(__fadd_rn(xx, nsq[jg]), -2.f * s);
                atomicMin(ex + r, packdi(d, (unsigned)jg));
            }
        }
    }
}

// -------------------- select exact winners --------------------
__global__ void sel_kernel(const int* __restrict__ list, const int* __restrict__ cnt,
                           const ull* __restrict__ ex, int* __restrict__ idx) {
    int i = blockIdx.x * blockDim.x + threadIdx.x;
    if (i < *cnt) { int r = list[i]; idx[r] = (int)(ex[r] & 0xffffffffu); }
}

// -------------------- gather q = emb[idx] (+ split), loss --------------------
__global__ void gather_loss(const float* __restrict__ emb, const int* __restrict__ idx,
                            const float* __restrict__ x, int ldx, float* __restrict__ q,
                            __half* __restrict__ qh, __half* __restrict__ ql) {
    int r = blockIdx.x;
    int j = idx[r];
    const float* e = emb + (size_t)j * D;
    const float* xr = x + (size_t)r * ldx;
    float* qr = q + (size_t)r * D;
    float ls = 0.f;
    for (int k = threadIdx.x; k < D; k += blockDim.x) {
        float ev = e[k];
        qr[k] = ev;
        __half hh = __float2half_rn(ev);
        qh[(size_t)r * D + k] = hh;
        ql[(size_t)r * D + k] = __float2half_rn(ev - __half2float(hh));
        float dd = ev - xr[k];
        ls += dd * dd;
    }
    #pragma unroll
    for (int o = 16; o; o >>= 1) ls += __shfl_xor_sync(0xffffffffu, ls, o);
    __shared__ float ws[8];
    int w = threadIdx.x >> 5;
    if ((threadIdx.x & 31) == 0) ws[w] = ls;
    __syncthreads();
    if (threadIdx.x == 0) {
        float s = 0.f;
        for (int i = 0; i < 8; i++) s += ws[i];
        atomicAdd(&g_loss, s);
    }
}

// -------------------- LayerNorm + leakyReLU + fused follow-up --------------------
template <int MODE>
__global__ void ln_kernel(const float* __restrict__ h,
                          const float* __restrict__ g, const float* __restrict__ be,
                          const float* __restrict__ z,
                          const float* __restrict__ gc_raw, const float* __restrict__ gf_raw,
                          float* __restrict__ out)
{
    int r = blockIdx.x;
    int j = threadIdx.x;
    float hv = h[(size_t)r * D + j];
    float s = hv, sq = hv * hv;
    #pragma unroll
    for (int o = 16; o; o >>= 1) {
        s += __shfl_xor_sync(0xffffffffu, s, o);
        sq += __shfl_xor_sync(0xffffffffu, sq, o);
    }
    __shared__ float s1[16], s2[16];
    int w = j >> 5, lane = j & 31;
    if (lane == 0) { s1[w] = s; s2[w] = sq; }
    __syncthreads();
    if (w == 0) {
        s = (lane < 16) ? s1[lane] : 0.f;
        sq = (lane < 16) ? s2[lane] : 0.f;
        #pragma unroll
        for (int o = 8; o; o >>= 1) {
            s += __shfl_xor_sync(0xffffffffu, s, o);
            sq += __shfl_xor_sync(0xffffffffu, sq, o);
        }
        if (lane == 0) { s1[0] = s; s2[0] = sq; }
    }
    __syncthreads();
    float mean = s1[0] * (1.f / D);
    float var = s2[0] * (1.f / D) - mean * mean;
    float y = (hv - mean) * rsqrtf(var + 1e-5f) * g[j] + be[j];
    float act = y > 0.f ? y : 0.1f * y;
    float gcv = 1.f / (1.f + expf(-gc_raw[0]));

    if (MODE == 0) {
        float rv = z[(size_t)r * 1024 + D + j] - gcv * act;
        g_ci[(size_t)r * D + j] = act;
        g_res[(size_t)r * D + j] = rv;
        __half hh = __float2half_rn(rv);
        g_res_h[(size_t)r * D + j] = hh;
        g_res_l[(size_t)r * D + j] = __float2half_rn(rv - __half2float(hh));
        float rq = rv * rv;
        #pragma unroll
        for (int o = 16; o; o >>= 1) rq += __shfl_xor_sync(0xffffffffu, rq, o);
        __syncthreads();
        if (lane == 0) s1[w] = rq;
        __syncthreads();
        if (j == 0) {
            float tt = 0.f;
            #pragma unroll
            for (int i = 0; i < 16; i++) tt += s1[i];
            g_xnsq_f[r] = tt;
        }
    } else {
        float gfv = 1.f / (1.f + expf(-gf_raw[0]));
        out[(size_t)r * 1024 + j] = g_qc[(size_t)r * D + j] + 0.1f * gfv * act;
        out[(size_t)r * 1024 + D + j] = g_qf[(size_t)r * D + j] + gcv * g_ci[(size_t)r * D + j];
        if (r == 0 && j == 0)
            out[(size_t)NROWS * 1024] = 1.25f * g_loss / (float)((size_t)NROWS * D);
    }
}

// -------------------- launch --------------------
#define SYMADDR(p, s) cudaGetSymbolAddress((void**)&p, s)

extern "C" void kernel_launch(void* const* d_in, const int* in_sizes, int n_in,
                              void* d_out, int out_size) {
    const float* z      = (const float*)d_in[0];
    const float* ce     = (const float*)d_in[1];
    const float* fe     = (const float*)d_in[2];
    const float* w_c2f  = (const float*)d_in[3];
    const float* b_c2f  = (const float*)d_in[4];
    const float* g_c2f  = (const float*)d_in[5];
    const float* be_c2f = (const float*)d_in[6];
    const float* w_f2c  = (const float*)d_in[7];
    const float* b_f2c  = (const float*)d_in[8];
    const float* g_f2c  = (const float*)d_in[9];
    const float* be_f2c = (const float*)d_in[10];
    const float* gc_raw = (const float*)d_in[11];
    const float* gf_raw = (const float*)d_in[12];
    float* out = (float*)d_out;

    float *nsq_c, *nsq_f, *xnsq_c, *xnsq_f, *qc, *qf, *res, *h;
    ull *b1c, *b2c, *b1f, *b2f, *exc, *exf;
    int *idx_c, *idx_f, *list_c, *list_f, *cnt_c, *cnt_f;
    __half *zc_h, *zc_l, *ce_h, *ce_l, *fe_h, *fe_l, *res_h, *res_l, *q_h, *q_l;
    __half *w1_h, *w1_l, *w2_h, *w2_l;
    SYMADDR(nsq_c, g_nsq_c);   SYMADDR(nsq_f, g_nsq_f);
    SYMADDR(xnsq_c, g_xnsq_c); SYMADDR(xnsq_f, g_xnsq_f);
    SYMADDR(b1c, g_b1c); SYMADDR(b2c, g_b2c); SYMADDR(b1f, g_b1f); SYMADDR(b2f, g_b2f);
    SYMADDR(exc, g_exc); SYMADDR(exf, g_exf);
    SYMADDR(idx_c, g_idx_c); SYMADDR(idx_f, g_idx_f);
    SYMADDR(list_c, g_list_c); SYMADDR(list_f, g_list_f);
    SYMADDR(cnt_c, g_cnt_c); SYMADDR(cnt_f, g_cnt_f);
    SYMADDR(qc, g_qc); SYMADDR(qf, g_qf); SYMADDR(res, g_res); SYMADDR(h, g_h);
    SYMADDR(zc_h, g_zc_h); SYMADDR(zc_l, g_zc_l);
    SYMADDR(ce_h, g_ce_h); SYMADDR(ce_l, g_ce_l);
    SYMADDR(fe_h, g_fe_h); SYMADDR(fe_l, g_fe_l);
    SYMADDR(res_h, g_res_h); SYMADDR(res_l, g_res_l);
    SYMADDR(q_h, g_q_h); SYMADDR(q_l, g_q_l);
    SYMADDR(w1_h, g_w1_h); SYMADDR(w1_l, g_w1_l);
    SYMADDR(w2_h, g_w2_h); SYMADDR(w2_l, g_w2_l);

    cudaFuncSetAttribute(mma_gemm<0>, cudaFuncAttributeMaxDynamicSharedMemorySize, SMEM_DYN);
    cudaFuncSetAttribute(mma_gemm<1>, cudaFuncAttributeMaxDynamicSharedMemorySize, SMEM_DYN);

    // launches 1-3 (prep), #4 = coarse VQ GEMM (profiled by ncu next round)
    init_kernel<<<NROWS / 256, 256>>>();
    zero_kernel<<<1, 32>>>();
    {
        int warps = CB + FB + NROWS + 2 * D;
        prep_split<<<(warps * 32 + 255) / 256, 256>>>(z, ce, fe, w_c2f, w_f2c);
    }
    // coarse VQ
    mma_gemm<0><<<dim3(NROWS / BM, CB / BN), 256, SMEM_DYN>>>(zc_h, zc_l, ce_h, ce_l, nsq_c, xnsq_c, b1c, b2c, nullptr);
    flag_kernel<<<NROWS / 256, 256>>>(b1c, b2c, idx_c, list_c, cnt_c);
    exact_kernel<<<CB / 16, 256>>>(z, 1024, ce, nsq_c, xnsq_c, list_c, cnt_c, exc);
    sel_kernel<<<NROWS / 256, 256>>>(list_c, cnt_c, exc, idx_c);
    gather_loss<<<NROWS, 256>>>(ce, idx_c, z, 1024, qc, q_h, q_l);
    // MLP c2f
    mma_gemm<1><<<dim3(NROWS / BM, D / BN), 256, SMEM_DYN>>>(q_h, q_l, w1_h, w1_l, b_c2f, nullptr, nullptr, nullptr, h);
    ln_kernel<0><<<NROWS, 512>>>(h, g_c2f, be_c2f, z, gc_raw, gf_raw, nullptr);
    // fine VQ
    mma_gemm<0><<<dim3(NROWS / BM, FB / BN), 256, SMEM_DYN>>>(res_h, res_l, fe_h, fe_l, nsq_f, xnsq_f, b1f, b2f, nullptr);
    flag_kernel<<<NROWS / 256, 256>>>(b1f, b2f, idx_f, list_f, cnt_f);
    exact_kernel<<<FB / 16, 256>>>(res, D, fe, nsq_f, xnsq_f, list_f, cnt_f, exf);
    sel_kernel<<<NROWS / 256, 256>>>(list_f, cnt_f, exf, idx_f);
    gather_loss<<<NROWS, 256>>>(fe, idx_f, res, D, qf, q_h, q_l);
    // MLP f2c
    mma_gemm<1><<<dim3(NROWS / BM, D / BN), 256, SMEM_DYN>>>(q_h, q_l, w2_h, w2_l, b_f2c, nullptr, nullptr, nullptr, h);
    ln_kernel<1><<<NROWS, 512>>>(h, g_f2c, be_f2c, z, gc_raw, gf_raw, out);
}

// round 9
// speedup vs baseline: 2.3860x; 1.0171x over previous
#include <cuda_runtime.h>
#include <cuda_fp16.h>
#include <cstdint>
#include <math.h>

#define NROWS 8192
#define D     512
#define CB    4096
#define FB    8192
#define BM    128
#define BN    128
#define KC    32
#define NCH   (D / KC)
#define THRESH 1e-4f
#define SMEM_DYN 98304

typedef unsigned long long ull;

// -------------------- device scratch --------------------
__device__ float g_nsq_c[CB], g_nsq_f[FB];
__device__ float g_xnsq_c[NROWS], g_xnsq_f[NROWS];
__device__ ull   g_b1c[NROWS], g_b2c[NROWS], g_b1f[NROWS], g_b2f[NROWS];
__device__ ull   g_exc[NROWS], g_exf[NROWS];
__device__ int   g_idx_c[NROWS], g_idx_f[NROWS];
__device__ int   g_list_c[NROWS], g_list_f[NROWS];
__device__ int   g_cnt_c, g_cnt_f;
__device__ float g_qc[NROWS * D], g_qf[NROWS * D];
__device__ float g_ci[NROWS * D], g_res[NROWS * D], g_h[NROWS * D];
__device__ __half g_zc_h[NROWS * D], g_zc_l[NROWS * D];
__device__ __half g_ce_h[CB * D],   g_ce_l[CB * D];
__device__ __half g_fe_h[FB * D],   g_fe_l[FB * D];
__device__ __half g_res_h[NROWS * D], g_res_l[NROWS * D];
__device__ __half g_q_h[NROWS * D],   g_q_l[NROWS * D];
__device__ __half g_w1_h[D * D], g_w1_l[D * D], g_w2_h[D * D], g_w2_l[D * D];
__device__ float g_loss;

// -------------------- helpers --------------------
__device__ __forceinline__ uint32_t smem_u32(const void* p) {
    uint32_t a;
    asm("{ .reg .u64 t; cvta.to.shared.u64 t, %1; cvt.u32.u64 %0, t; }" : "=r"(a) : "l"(p));
    return a;
}
// 64B-row swizzle: XOR 16B-segment bits [5:4] with row bits (o[8:7])
#define SWZ32(o) ((o) ^ (((o) >> 3) & 0x30))
#define LDM4(r0, r1, r2, r3, a) \
    asm volatile("ldmatrix.sync.aligned.m8n8.x4.shared.b16 {%0,%1,%2,%3}, [%4];" \
        : "=r"(r0), "=r"(r1), "=r"(r2), "=r"(r3) : "r"(a))
#define MMA_F16(c, a, b) \
    asm volatile("mma.sync.aligned.m16n8k16.row.col.f32.f16.f16.f32 " \
        "{%0,%1,%2,%3}, {%4,%5,%6,%7}, {%8,%9}, {%0,%1,%2,%3};" \
        : "+f"((c)[0]), "+f"((c)[1]), "+f"((c)[2]), "+f"((c)[3]) \
        : "r"((a)[0]), "r"((a)[1]), "r"((a)[2]), "r"((a)[3]), "r"((b)[0]), "r"((b)[1]))
#define CP_ASYNC16(dst, src) \
    asm volatile("cp.async.cg.shared.global [%0], [%1], 16;" :: "r"(dst), "l"(src))
#define CP_COMMIT() asm volatile("cp.async.commit_group;")
#define CP_WAIT1()  asm volatile("cp.async.wait_group 1;")

__device__ __forceinline__ ull packdi(float d, unsigned j) {
    unsigned u = __float_as_uint(d);
    u = (u & 0x80000000u) ? ~u : (u | 0x80000000u);
    return ((ull)u << 32) | (ull)j;
}
__device__ __forceinline__ float unpackd(ull p) {
    unsigned u = (unsigned)(p >> 32);
    u = (u & 0x80000000u) ? (u & 0x7fffffffu) : ~u;
    return __uint_as_float(u);
}
__device__ __forceinline__ void top2ins(ull& m1, ull& m2, ull p) {
    if (p < m1) { m2 = m1; m1 = p; }
    else if (p < m2) m2 = p;
}

// -------------------- launch 1: init best arrays --------------------
__global__ void init_kernel() {
    int r = blockIdx.x * blockDim.x + threadIdx.x;
    if (r < NROWS) {
        g_b1c[r] = ~0ull; g_b2c[r] = ~0ull;
        g_b1f[r] = ~0ull; g_b2f[r] = ~0ull;
        g_exc[r] = ~0ull; g_exf[r] = ~0ull;
    }
}
// -------------------- launch 2: zero scalars --------------------
__global__ void zero_kernel() {
    if (threadIdx.x == 0) { g_loss = 0.f; g_cnt_c = 0; g_cnt_f = 0; }
}

// -------------------- launch 3: fused norms + fp16 hi/lo splits --------------------
__global__ void prep_split(const float* __restrict__ z,
                           const float* __restrict__ ce, const float* __restrict__ fe,
                           const float* __restrict__ w1, const float* __restrict__ w2) {
    int gw = (blockIdx.x * blockDim.x + threadIdx.x) >> 5;
    int lane = threadIdx.x & 31;
    const float* src;
    __half *hi, *lo;
    float* nrm = nullptr;
    if (gw < CB) {
        src = ce + (size_t)gw * D; hi = g_ce_h + (size_t)gw * D; lo = g_ce_l + (size_t)gw * D;
        nrm = g_nsq_c + gw;
    } else if (gw < CB + FB) {
        int r = gw - CB;
        src = fe + (size_t)r * D; hi = g_fe_h + (size_t)r * D; lo = g_fe_l + (size_t)r * D;
        nrm = g_nsq_f + r;
    } else if (gw < CB + FB + NROWS) {
        int r = gw - CB - FB;
        src = z + (size_t)r * 1024; hi = g_zc_h + (size_t)r * D; lo = g_zc_l + (size_t)r * D;
        nrm = g_xnsq_c + r;
    } else if (gw < CB + FB + NROWS + D) {
        int r = gw - CB - FB - NROWS;
        src = w1 + (size_t)r * D; hi = g_w1_h + (size_t)r * D; lo = g_w1_l + (size_t)r * D;
    } else if (gw < CB + FB + NROWS + 2 * D) {
        int r = gw - CB - FB - NROWS - D;
        src = w2 + (size_t)r * D; hi = g_w2_h + (size_t)r * D; lo = g_w2_l + (size_t)r * D;
    } else return;

    float s = 0.f;
    #pragma unroll
    for (int it = 0; it < 4; it++) {
        int c = lane * 4 + it * 128;
        float4 v = *(const float4*)(src + c);
        s += v.x * v.x + v.y * v.y + v.z * v.z + v.w * v.w;
        __half hs[4], ls[4];
        hs[0] = __float2half_rn(v.x); ls[0] = __float2half_rn(v.x - __half2float(hs[0]));
        hs[1] = __float2half_rn(v.y); ls[1] = __float2half_rn(v.y - __half2float(hs[1]));
        hs[2] = __float2half_rn(v.z); ls[2] = __float2half_rn(v.z - __half2float(hs[2]));
        hs[3] = __float2half_rn(v.w); ls[3] = __float2half_rn(v.w - __half2float(hs[3]));
        *(uint2*)(hi + c) = *(uint2*)hs;
        *(uint2*)(lo + c) = *(uint2*)ls;
    }
    if (nrm) {
        #pragma unroll
        for (int o = 16; o; o >>= 1) s += __shfl_xor_sync(0xffffffffu, s, o);
        if (lane == 0) *nrm = s;
    }
}

// -------------------- HMMA fp16 3-pass GEMM, 3-stage cp.async pipeline --------------------
// MODE 0: VQ top-2 of d = fl(fl(xx+ee) - 2*dot) ; MODE 1: out = dot + bias
template <int MODE>
__global__ __launch_bounds__(256, 2) void mma_gemm(
    const __half* __restrict__ Ah, const __half* __restrict__ Al,
    const __half* __restrict__ Bh, const __half* __restrict__ Bl,
    const float* __restrict__ aux, const float* __restrict__ xnsq,
    ull* __restrict__ best1, ull* __restrict__ best2,
    float* __restrict__ out)
{
    extern __shared__ char sm[];
    __shared__ ull sb1[BM], sb2[BM];
    const int t = threadIdx.x;
    const int lane = t & 31, wid = t >> 5;
    const int warp_m = wid & 1, warp_n = wid >> 1;
    const int row0 = blockIdx.x * BM, col0 = blockIdx.y * BN;
    const uint32_t smb = smem_u32(sm);

    if (MODE == 0 && t < BM) { sb1[t] = ~0ull; sb2[t] = ~0ull; }

    float acc[4][4][4];
    #pragma unroll
    for (int i = 0; i < 4; i++)
        #pragma unroll
        for (int j = 0; j < 4; j++)
            #pragma unroll
            for (int k = 0; k < 4; k++) acc[i][j][k] = 0.f;

    // per-thread load mapping: row = t>>1, 16-elt segment = t&1
    const int lrow = t >> 1, lh = t & 1;
    const size_t aoff = (size_t)(row0 + lrow) * D + lh * 16;
    const size_t boff = (size_t)(col0 + lrow) * D + lh * 16;
    const uint32_t st0 = SWZ32((uint32_t)(lrow * 64 + lh * 32));
    const uint32_t st1 = SWZ32((uint32_t)(lrow * 64 + lh * 32 + 16));

    // stage s at smb + s*32768; arrays AH +0, AL +8192, BH +16384, BL +24576
    #define ISSUE(c) do { \
        uint32_t bb = smb + (uint32_t)((c) % 3) * 32768u; \
        const int kb = (c) * KC; \
        CP_ASYNC16(bb + st0,           (const char*)(Ah + aoff + kb)); \
        CP_ASYNC16(bb + st1,           (const char*)(Ah + aoff + kb + 8)); \
        CP_ASYNC16(bb + 8192u  + st0,  (const char*)(Al + aoff + kb)); \
        CP_ASYNC16(bb + 8192u  + st1,  (const char*)(Al + aoff + kb + 8)); \
        CP_ASYNC16(bb + 16384u + st0,  (const char*)(Bh + boff + kb)); \
        CP_ASYNC16(bb + 16384u + st1,  (const char*)(Bh + boff + kb + 8)); \
        CP_ASYNC16(bb + 24576u + st0,  (const char*)(Bl + boff + kb)); \
        CP_ASYNC16(bb + 24576u + st1,  (const char*)(Bl + boff + kb + 8)); \
        CP_COMMIT(); \
    } while (0)

    ISSUE(0);
    ISSUE(1);

    #pragma unroll 1
    for (int c = 0; c < NCH; c++) {
        const uint32_t bb = smb + (uint32_t)(c % 3) * 32768u;
        const uint32_t AHs = bb, ALs = bb + 8192u, BHs = bb + 16384u, BLs = bb + 24576u;
        CP_WAIT1();          // this thread's group c complete (<=1 pending)
        __syncthreads();     // publish group c; all warps done with chunk c-1
        if (c + 2 < NCH) ISSUE(c + 2);   // into stage (c+2)%3 == (c-1)%3, freed by sync
        #pragma unroll
        for (int k16 = 0; k16 < 2; k16++) {
            uint32_t bhf[4][2], blf[4][2], ah[4][4], al[4][4];
            // B hi frags
            #pragma unroll
            for (int nt2 = 0; nt2 < 2; nt2++) {
                int nrow = warp_n * 32 + nt2 * 16 + (lane & 7) + ((lane & 16) ? 8 : 0);
                int kbyte = k16 * 32 + ((lane >> 3) & 1) * 16;
                uint32_t off = SWZ32((uint32_t)(nrow * 64 + kbyte));
                LDM4(bhf[nt2 * 2][0], bhf[nt2 * 2][1], bhf[nt2 * 2 + 1][0], bhf[nt2 * 2 + 1][1], BHs + off);
            }
            // A hi frags
            #pragma unroll
            for (int mt = 0; mt < 4; mt++) {
                int mrow = warp_m * 64 + mt * 16 + (lane & 15);
                int kbyte = k16 * 32 + (lane >> 4) * 16;
                uint32_t off = SWZ32((uint32_t)(mrow * 64 + kbyte));
                LDM4(ah[mt][0], ah[mt][1], ah[mt][2], ah[mt][3], AHs + off);
            }
            // B lo frags (issued early; latency covered by hh MMAs)
            #pragma unroll
            for (int nt2 = 0; nt2 < 2; nt2++) {
                int nrow = warp_n * 32 + nt2 * 16 + (lane & 7) + ((lane & 16) ? 8 : 0);
                int kbyte = k16 * 32 + ((lane >> 3) & 1) * 16;
                uint32_t off = SWZ32((uint32_t)(nrow * 64 + kbyte));
                LDM4(blf[nt2 * 2][0], blf[nt2 * 2][1], blf[nt2 * 2 + 1][0], blf[nt2 * 2 + 1][1], BLs + off);
            }
            // hh
            #pragma unroll
            for (int mt = 0; mt < 4; mt++)
                #pragma unroll
                for (int nt = 0; nt < 4; nt++) MMA_F16(acc[mt][nt], ah[mt], bhf[nt]);
            // A lo frags (issued early; latency covered by hl MMAs)
            #pragma unroll
            for (int mt = 0; mt < 4; mt++) {
                int mrow = warp_m * 64 + mt * 16 + (lane & 15);
                int kbyte = k16 * 32 + (lane >> 4) * 16;
                uint32_t off = SWZ32((uint32_t)(mrow * 64 + kbyte));
                LDM4(al[mt][0], al[mt][1], al[mt][2], al[mt][3], ALs + off);
            }
            // hl
            #pragma unroll
            for (int mt = 0; mt < 4; mt++)
                #pragma unroll
                for (int nt = 0; nt < 4; nt++) MMA_F16(acc[mt][nt], ah[mt], blf[nt]);
            // lh
            #pragma unroll
            for (int mt = 0; mt < 4; mt++)
                #pragma unroll
                for (int nt = 0; nt < 4; nt++) MMA_F16(acc[mt][nt], al[mt], bhf[nt]);
        }
    }

    const int g = lane >> 2, tg = lane & 3;
    if (MODE == 0) {
        #pragma unroll
        for (int mt = 0; mt < 4; mt++) {
            #pragma unroll
            for (int h8 = 0; h8 < 2; h8++) {
                int lrow2 = warp_m * 64 + mt * 16 + g + h8 * 8;
                float xx = xnsq[row0 + lrow2];
                ull m1 = ~0ull, m2 = ~0ull;
                #pragma unroll
                for (int nt = 0; nt < 4; nt++) {
                    int colg = col0 + warp_n * 32 + nt * 8 + tg * 2;
                    float d0 = __fadd_rn(__fadd_rn(xx, aux[colg]), -2.f * acc[mt][nt][h8 * 2 + 0]);
                    float d1 = __fadd_rn(__fadd_rn(xx, aux[colg + 1]), -2.f * acc[mt][nt][h8 * 2 + 1]);
                    top2ins(m1, m2, packdi(d0, (unsigned)colg));
                    top2ins(m1, m2, packdi(d1, (unsigned)(colg + 1)));
                }
                #pragma unroll
                for (int o = 1; o <= 2; o <<= 1) {
                    ull o1 = __shfl_xor_sync(0xffffffffu, m1, o);
                    ull o2 = __shfl_xor_sync(0xffffffffu, m2, o);
                    ull n1 = o1 < m1 ? o1 : m1;
                    ull hi = o1 > m1 ? o1 : m1;
                    ull lo2 = o2 < m2 ? o2 : m2;
                    m2 = hi < lo2 ? hi : lo2;
                    m1 = n1;
                }
                if (tg == 0) {
                    ull old = atomicMin(&sb1[lrow2], m1);
                    atomicMin(&sb2[lrow2], old > m1 ? old : m1);
                    atomicMin(&sb2[lrow2], m2);
                }
            }
        }
        __syncthreads();
        if (t < BM) {
            ull s1 = sb1[t], s2 = sb2[t];
            ull old = atomicMin(&best1[row0 + t], s1);
            atomicMin(&best2[row0 + t], old > s1 ? old : s1);
            atomicMin(&best2[row0 + t], s2);
        }
    } else {
        #pragma unroll
        for (int mt = 0; mt < 4; mt++) {
            #pragma unroll
            for (int h8 = 0; h8 < 2; h8++) {
                int row = row0 + warp_m * 64 + mt * 16 + g + h8 * 8;
                #pragma unroll
                for (int nt = 0; nt < 4; nt++) {
                    int colg = col0 + warp_n * 32 + nt * 8 + tg * 2;
                    float2 o2 = make_float2(acc[mt][nt][h8 * 2 + 0] + aux[colg],
                                            acc[mt][nt][h8 * 2 + 1] + aux[colg + 1]);
                    *(float2*)&out[(size_t)row * D + colg] = o2;
                }
            }
        }
    }
    #undef ISSUE
}

// -------------------- flag: compact near-tie rows --------------------
__global__ void flag_kernel(const ull* __restrict__ b1, const ull* __restrict__ b2,
                            int* __restrict__ idx, int* __restrict__ list, int* __restrict__ cnt) {
    int r = blockIdx.x * blockDim.x + threadIdx.x;
    if (r >= NROWS) return;
    ull p1 = b1[r];
    idx[r] = (int)(p1 & 0xffffffffu);
    if (unpackd(b2[r]) - unpackd(p1) <= THRESH) {
        int pos = atomicAdd(cnt, 1);
        list[pos] = r;
    }
}

// -------------------- exact re-decide (emb-tiled over flagged rows) --------------------
__global__ void exact_kernel(const float* __restrict__ x, int ldx,
                             const float* __restrict__ emb,
                             const float* __restrict__ nsq, const float* __restrict__ xnsq,
                             const int* __restrict__ list, const int* __restrict__ cnt,
                             ull* __restrict__ ex) {
    int n = *cnt;
    if (n == 0) return;
    __shared__ float es[16 * 512];
    __shared__ float xs[512];
    const int t = threadIdx.x, lane = t & 31, w = t >> 5;
    const float* ep = emb + (size_t)blockIdx.x * 16 * 512;
    for (int i = t; i < 16 * 512 / 4; i += 256) ((float4*)es)[i] = ((const float4*)ep)[i];
    for (int i = 0; i < n; i++) {
        int r = list[i];
        __syncthreads();
        if (t < 128) ((float4*)xs)[t] = *(const float4*)(x + (size_t)r * ldx + t * 4);
        __syncthreads();
        float xx = xnsq[r];
        #pragma unroll
        for (int e2 = 0; e2 < 2; e2++) {
            int j = w * 2 + e2;
            const float* er = es + j * 512;
            float s = 0.f;
            for (int k = lane; k < 512; k += 32) s = fmaf(er[k], xs[k], s);
            #pragma unroll
            for (int o = 16; o; o >>= 1) s += __shfl_xor_sync(0xffffffffu, s, o);
            if (lane == 0) {
                int jg = blockIdx.x * 16 + j;
                float d = __fadd_rn(__fadd_rn(xx, nsq[jg]), -2.f * s);
                atomicMin(ex + r, packdi(d, (unsigned)jg));
            }
        }
    }
}

// -------------------- select exact winners --------------------
__global__ void sel_kernel(const int* __restrict__ list, const int* __restrict__ cnt,
                           const ull* __restrict__ ex, int* __restrict__ idx) {
    int i = blockIdx.x * blockDim.x + threadIdx.x;
    if (i < *cnt) { int r = list[i]; idx[r] = (int)(ex[r] & 0xffffffffu); }
}

// -------------------- gather q = emb[idx] (+ split), loss --------------------
__global__ void gather_loss(const float* __restrict__ emb, const int* __restrict__ idx,
                            const float* __restrict__ x, int ldx, float* __restrict__ q,
                            __half* __restrict__ qh, __half* __restrict__ ql) {
    int r = blockIdx.x;
    int j = idx[r];
    const float* e = emb + (size_t)j * D;
    const float* xr = x + (size_t)r * ldx;
    float* qr = q + (size_t)r * D;
    float ls = 0.f;
    for (int k = threadIdx.x; k < D; k += blockDim.x) {
        float ev = e[k];
        qr[k] = ev;
        __half hh = __float2half_rn(ev);
        qh[(size_t)r * D + k] = hh;
        ql[(size_t)r * D + k] = __float2half_rn(ev - __half2float(hh));
        float dd = ev - xr[k];
        ls += dd * dd;
    }
    #pragma unroll
    for (int o = 16; o; o >>= 1) ls += __shfl_xor_sync(0xffffffffu, ls, o);
    __shared__ float ws[8];
    int w = threadIdx.x >> 5;
    if ((threadIdx.x & 31) == 0) ws[w] = ls;
    __syncthreads();
    if (threadIdx.x == 0) {
        float s = 0.f;
        for (int i = 0; i < 8; i++) s += ws[i];
        atomicAdd(&g_loss, s);
    }
}

// -------------------- LayerNorm + leakyReLU + fused follow-up --------------------
template <int MODE>
__global__ void ln_kernel(const float* __restrict__ h,
                          const float* __restrict__ g, const float* __restrict__ be,
                          const float* __restrict__ z,
                          const float* __restrict__ gc_raw, const float* __restrict__ gf_raw,
                          float* __restrict__ out)
{
    int r = blockIdx.x;
    int j = threadIdx.x;
    float hv = h[(size_t)r * D + j];
    float s = hv, sq = hv * hv;
    #pragma unroll
    for (int o = 16; o; o >>= 1) {
        s += __shfl_xor_sync(0xffffffffu, s, o);
        sq += __shfl_xor_sync(0xffffffffu, sq, o);
    }
    __shared__ float s1[16], s2[16];
    int w = j >> 5, lane = j & 31;
    if (lane == 0) { s1[w] = s; s2[w] = sq; }
    __syncthreads();
    if (w == 0) {
        s = (lane < 16) ? s1[lane] : 0.f;
        sq = (lane < 16) ? s2[lane] : 0.f;
        #pragma unroll
        for (int o = 8; o; o >>= 1) {
            s += __shfl_xor_sync(0xffffffffu, s, o);
            sq += __shfl_xor_sync(0xffffffffu, sq, o);
        }
        if (lane == 0) { s1[0] = s; s2[0] = sq; }
    }
    __syncthreads();
    float mean = s1[0] * (1.f / D);
    float var = s2[0] * (1.f / D) - mean * mean;
    float y = (hv - mean) * rsqrtf(var + 1e-5f) * g[j] + be[j];
    float act = y > 0.f ? y : 0.1f * y;
    float gcv = 1.f / (1.f + expf(-gc_raw[0]));

    if (MODE == 0) {
        float rv = z[(size_t)r * 1024 + D + j] - gcv * act;
        g_ci[(size_t)r * D + j] = act;
        g_res[(size_t)r * D + j] = rv;
        __half hh = __float2half_rn(rv);
        g_res_h[(size_t)r * D + j] = hh;
        g_res_l[(size_t)r * D + j] = __float2half_rn(rv - __half2float(hh));
        float rq = rv * rv;
        #pragma unroll
        for (int o = 16; o; o >>= 1) rq += __shfl_xor_sync(0xffffffffu, rq, o);
        __syncthreads();
        if (lane == 0) s1[w] = rq;
        __syncthreads();
        if (j == 0) {
            float tt = 0.f;
            #pragma unroll
            for (int i = 0; i < 16; i++) tt += s1[i];
            g_xnsq_f[r] = tt;
        }
    } else {
        float gfv = 1.f / (1.f + expf(-gf_raw[0]));
        out[(size_t)r * 1024 + j] = g_qc[(size_t)r * D + j] + 0.1f * gfv * act;
        out[(size_t)r * 1024 + D + j] = g_qf[(size_t)r * D + j] + gcv * g_ci[(size_t)r * D + j];
        if (r == 0 && j == 0)
            out[(size_t)NROWS * 1024] = 1.25f * g_loss / (float)((size_t)NROWS * D);
    }
}

// -------------------- launch --------------------
#define SYMADDR(p, s) cudaGetSymbolAddress((void**)&p, s)

extern "C" void kernel_launch(void* const* d_in, const int* in_sizes, int n_in,
                              void* d_out, int out_size) {
    const float* z      = (const float*)d_in[0];
    const float* ce     = (const float*)d_in[1];
    const float* fe     = (const float*)d_in[2];
    const float* w_c2f  = (const float*)d_in[3];
    const float* b_c2f  = (const float*)d_in[4];
    const float* g_c2f  = (const float*)d_in[5];
    const float* be_c2f = (const float*)d_in[6];
    const float* w_f2c  = (const float*)d_in[7];
    const float* b_f2c  = (const float*)d_in[8];
    const float* g_f2c  = (const float*)d_in[9];
    const float* be_f2c = (const float*)d_in[10];
    const float* gc_raw = (const float*)d_in[11];
    const float* gf_raw = (const float*)d_in[12];
    float* out = (float*)d_out;

    float *nsq_c, *nsq_f, *xnsq_c, *xnsq_f, *qc, *qf, *res, *h;
    ull *b1c, *b2c, *b1f, *b2f, *exc, *exf;
    int *idx_c, *idx_f, *list_c, *list_f, *cnt_c, *cnt_f;
    __half *zc_h, *zc_l, *ce_h, *ce_l, *fe_h, *fe_l, *res_h, *res_l, *q_h, *q_l;
    __half *w1_h, *w1_l, *w2_h, *w2_l;
    SYMADDR(nsq_c, g_nsq_c);   SYMADDR(nsq_f, g_nsq_f);
    SYMADDR(xnsq_c, g_xnsq_c); SYMADDR(xnsq_f, g_xnsq_f);
    SYMADDR(b1c, g_b1c); SYMADDR(b2c, g_b2c); SYMADDR(b1f, g_b1f); SYMADDR(b2f, g_b2f);
    SYMADDR(exc, g_exc); SYMADDR(exf, g_exf);
    SYMADDR(idx_c, g_idx_c); SYMADDR(idx_f, g_idx_f);
    SYMADDR(list_c, g_list_c); SYMADDR(list_f, g_list_f);
    SYMADDR(cnt_c, g_cnt_c); SYMADDR(cnt_f, g_cnt_f);
    SYMADDR(qc, g_qc); SYMADDR(qf, g_qf); SYMADDR(res, g_res); SYMADDR(h, g_h);
    SYMADDR(zc_h, g_zc_h); SYMADDR(zc_l, g_zc_l);
    SYMADDR(ce_h, g_ce_h); SYMADDR(ce_l, g_ce_l);
    SYMADDR(fe_h, g_fe_h); SYMADDR(fe_l, g_fe_l);
    SYMADDR(res_h, g_res_h); SYMADDR(res_l, g_res_l);
    SYMADDR(q_h, g_q_h); SYMADDR(q_l, g_q_l);
    SYMADDR(w1_h, g_w1_h); SYMADDR(w1_l, g_w1_l);
    SYMADDR(w2_h, g_w2_h); SYMADDR(w2_l, g_w2_l);

    cudaFuncSetAttribute(mma_gemm<0>, cudaFuncAttributeMaxDynamicSharedMemorySize, SMEM_DYN);
    cudaFuncSetAttribute(mma_gemm<1>, cudaFuncAttributeMaxDynamicSharedMemorySize, SMEM_DYN);

    init_kernel<<<NROWS / 256, 256>>>();
    zero_kernel<<<1, 32>>>();
    {
        int warps = CB + FB + NROWS + 2 * D;
        prep_split<<<(warps * 32 + 255) / 256, 256>>>(z, ce, fe, w_c2f, w_f2c);
    }
    // coarse VQ  (launch #4 — profiled)
    mma_gemm<0><<<dim3(NROWS / BM, CB / BN), 256, SMEM_DYN>>>(zc_h, zc_l, ce_h, ce_l, nsq_c, xnsq_c, b1c, b2c, nullptr);
    flag_kernel<<<NROWS / 256, 256>>>(b1c, b2c, idx_c, list_c, cnt_c);
    exact_kernel<<<CB / 16, 256>>>(z, 1024, ce, nsq_c, xnsq_c, list_c, cnt_c, exc);
    sel_kernel<<<NROWS / 256, 256>>>(list_c, cnt_c, exc, idx_c);
    gather_loss<<<NROWS, 256>>>(ce, idx_c, z, 1024, qc, q_h, q_l);
    // MLP c2f
    mma_gemm<1><<<dim3(NROWS / BM, D / BN), 256, SMEM_DYN>>>(q_h, q_l, w1_h, w1_l, b_c2f, nullptr, nullptr, nullptr, h);
    ln_kernel<0><<<NROWS, 512>>>(h, g_c2f, be_c2f, z, gc_raw, gf_raw, nullptr);
    // fine VQ
    mma_gemm<0><<<dim3(NROWS / BM, FB / BN), 256, SMEM_DYN>>>(res_h, res_l, fe_h, fe_l, nsq_f, xnsq_f, b1f, b2f, nullptr);
    flag_kernel<<<NROWS / 256, 256>>>(b1f, b2f, idx_f, list_f, cnt_f);
    exact_kernel<<<FB / 16, 256>>>(res, D, fe, nsq_f, xnsq_f, list_f, cnt_f, exf);
    sel_kernel<<<NROWS / 256, 256>>>(list_f, cnt_f, exf, idx_f);
    gather_loss<<<NROWS, 256>>>(fe, idx_f, res, D, qf, q_h, q_l);
    // MLP f2c
    mma_gemm<1><<<dim3(NROWS / BM, D / BN), 256, SMEM_DYN>>>(q_h, q_l, w2_h, w2_l, b_f2c, nullptr, nullptr, nullptr, h);
    ln_kernel<1><<<NROWS, 512>>>(h, g_f2c, be_f2c, z, gc_raw, gf_raw, out);
}